// round 7
// baseline (speedup 1.0000x reference)
#include <cuda_runtime.h>
#include <cuda_bf16.h>
#include <cstdint>

// ---------------------------------------------------------------------------
// GIN on GB300 (compute_103-portable): scatter-sum (fp32 red.global) +
// bf16 error-compensated split GEMMs on mma.sync tensor cores.
//   C = Ahi@Bhi + Ahi@Blo + Alo@Bhi  (fp32 accumulate)  ~ fp32 GEMM, ~1e-5
// A is kept fp32 end-to-end; the hi/lo split happens inside the GEMM load
// stage (registers -> two bf16 smem tiles). Weights pre-split once.
// ---------------------------------------------------------------------------

#define N_NODES 50000
#define M_PAD   50048      // 128 * 391
#define D_MAX   256

// Static scratch (zero-initialized; padding rows are never written -> stay 0).
__device__ float g_f0[(size_t)M_PAD * D_MAX];          // aggregate / GEMM input
__device__ float g_f1[(size_t)M_PAD * D_MAX];          // intermediates
__device__ float g_f2[(size_t)M_PAD * D_MAX];          // h2 (scatter source)
__device__ __nv_bfloat16 g_wthi[4][256 * 256];         // transposed weights [N][K]
__device__ __nv_bfloat16 g_wtlo[4][256 * 256];
__device__ int g_idx_is64;

// ---------------------------------------------------------------------------
// PTX helpers (portable: ldmatrix + mma.sync, sm_80+)
// ---------------------------------------------------------------------------
static __device__ __forceinline__ uint32_t smem_u32(const void* p) {
    uint32_t a;
    asm("{ .reg .u64 t; cvta.to.shared.u64 t, %1; cvt.u32.u64 %0, t; }" : "=r"(a) : "l"(p));
    return a;
}

static __device__ __forceinline__ void ldsm_x4(uint32_t* r, uint32_t addr) {
    asm volatile("ldmatrix.sync.aligned.m8n8.x4.shared.b16 {%0,%1,%2,%3}, [%4];"
                 : "=r"(r[0]), "=r"(r[1]), "=r"(r[2]), "=r"(r[3]) : "r"(addr));
}

static __device__ __forceinline__ void mma16816(float* c, const uint32_t* a, const uint32_t* b) {
    asm volatile("mma.sync.aligned.m16n8k16.row.col.f32.bf16.bf16.f32 "
                 "{%0,%1,%2,%3}, {%4,%5,%6,%7}, {%8,%9}, {%0,%1,%2,%3};"
                 : "+f"(c[0]), "+f"(c[1]), "+f"(c[2]), "+f"(c[3])
                 : "r"(a[0]), "r"(a[1]), "r"(a[2]), "r"(a[3]), "r"(b[0]), "r"(b[1]));
}

// ---------------------------------------------------------------------------
// Small utility kernels
// ---------------------------------------------------------------------------
__global__ void detect_idx_kernel(const long long* __restrict__ ei) {
    if (threadIdx.x == 0 && blockIdx.x == 0) {
        int is64 = 1;
        #pragma unroll 1
        for (int i = 0; i < 64; ++i) {
            long long v = ei[i];
            if (v < 0 || v >= (long long)N_NODES) { is64 = 0; break; }
        }
        g_idx_is64 = is64;
    }
}

__global__ void copy_f4(const float* __restrict__ src, float* __restrict__ dst, int n4) {
    int i = blockIdx.x * blockDim.x + threadIdx.x;
    if (i < n4) reinterpret_cast<float4*>(dst)[i] = reinterpret_cast<const float4*>(src)[i];
}

// One kernel prepping all 4 weights: W[K,N] fp32 -> Wt_hi/Wt_lo [N,K] bf16.
__global__ void prep_weights_all(const float* __restrict__ W1a, const float* __restrict__ W2a,
                                 const float* __restrict__ W1b, const float* __restrict__ W2b,
                                 __nv_bfloat16* __restrict__ hi, __nv_bfloat16* __restrict__ lo) {
    int i = blockIdx.x * blockDim.x + threadIdx.x;   // 0 .. 196608
    const float* W; int K, N, base, li;
    if (i < 32768)        { W = W1a; K = 128; N = 256; base = 0;          li = i; }
    else if (i < 98304)   { W = W2a; K = 256; N = 256; base = 1 * 65536;  li = i - 32768; }
    else if (i < 163840)  { W = W1b; K = 256; N = 256; base = 2 * 65536;  li = i - 98304; }
    else if (i < 196608)  { W = W2b; K = 256; N = 128; base = 3 * 65536;  li = i - 163840; }
    else return;
    int n = li / K, k = li % K;
    float v = W[(size_t)k * N + n];
    __nv_bfloat16 h = __float2bfloat16(v);
    hi[base + li] = h;
    lo[base + li] = __float2bfloat16(v - __bfloat162float(h));
}

// ---------------------------------------------------------------------------
// Scatter-add (fp32, red.global.add.v4)
// ---------------------------------------------------------------------------
template<int D4_LOG2>
__global__ void scatter_add_kernel(const float* __restrict__ feat,
                                   float* __restrict__ out,
                                   const void* __restrict__ ei,
                                   int E) {
    const int D4 = 1 << D4_LOG2;
    const int D  = D4 * 4;
    int t = blockIdx.x * blockDim.x + threadIdx.x;
    int e = t >> D4_LOG2;
    int c = t & (D4 - 1);
    if (e >= E) return;

    int s, d;
    if (g_idx_is64) {
        const long long* p = (const long long*)ei;
        s = (int)p[e];
        d = (int)p[e + E];
    } else {
        const int* p = (const int*)ei;
        s = p[e];
        d = p[e + E];
    }
    s = min(max(s, 0), N_NODES - 1);
    d = min(max(d, 0), N_NODES - 1);

    const float4 v = *reinterpret_cast<const float4*>(feat + (size_t)s * D + c * 4);
    float* p = out + (size_t)d * D + c * 4;
    asm volatile("red.global.add.v4.f32 [%0], {%1,%2,%3,%4};"
                 :: "l"(p), "f"(v.x), "f"(v.y), "f"(v.z), "f"(v.w)
                 : "memory");
}

// ---------------------------------------------------------------------------
// mma.sync GEMM: C[M,N] = A[M,K]@B^T, A fp32 (split to bf16 hi/lo in-kernel),
// B = pre-split transposed weights [N,K] bf16 hi/lo.
// CTA tile 128x128, BK=32, 256 threads (8 warps, 2x4), warp tile 64x32.
// Double-buffered smem, register-staged prefetch, one __syncthreads per stage.
// EPI: 0 = fp32 (no relu), 1 = relu fp32, 2 = relu fp32 dual-store.
// A row loads unguarded (buffers padded to M_PAD, padding rows zero).
// ---------------------------------------------------------------------------
template<int EPI>
__global__ __launch_bounds__(256)
void mma_gemm(const float* __restrict__ A,
              const __nv_bfloat16* __restrict__ Bth, const __nv_bfloat16* __restrict__ Btl,
              const float* __restrict__ bias,
              float* __restrict__ out0, float* __restrict__ out1,
              int M, int K, int N) {
    constexpr int BM = 128, BK = 32, LDS = BK + 8;   // pad -> conflict-free ldmatrix
    __shared__ __nv_bfloat16 Ah[2][BM][LDS];
    __shared__ __nv_bfloat16 Al[2][BM][LDS];
    __shared__ __nv_bfloat16 Bh[2][BM][LDS];
    __shared__ __nv_bfloat16 Bl[2][BM][LDS];

    const int tid  = threadIdx.x;
    const int wid  = tid >> 5;
    const int lane = tid & 31;
    const int bm = blockIdx.y * 128;
    const int bn = blockIdx.x * 128;

    const int wm = (wid >> 2) * 64;   // warp m offset: 0 or 64
    const int wn = (wid & 3) * 32;    // warp n offset: 0,32,64,96

    // Load mapping: row = tid>>1 (0..127), col = (tid&1)*16; 16 elems/thread.
    const int l_row = tid >> 1;
    const int l_col = (tid & 1) * 16;

    const float*         a_ptr  = A   + (size_t)(bm + l_row) * K + l_col;
    const __nv_bfloat16* bh_ptr = Bth + (size_t)(bn + l_row) * K + l_col;
    const __nv_bfloat16* bl_ptr = Btl + (size_t)(bn + l_row) * K + l_col;

    float acc[4][4][4];
    #pragma unroll
    for (int mf = 0; mf < 4; ++mf)
        #pragma unroll
        for (int nf = 0; nf < 4; ++nf)
            #pragma unroll
            for (int c = 0; c < 4; ++c)
                acc[mf][nf][c] = 0.0f;

    const uint32_t ah_s[2] = { smem_u32(&Ah[0][0][0]), smem_u32(&Ah[1][0][0]) };
    const uint32_t al_s[2] = { smem_u32(&Al[0][0][0]), smem_u32(&Al[1][0][0]) };
    const uint32_t bh_s[2] = { smem_u32(&Bh[0][0][0]), smem_u32(&Bh[1][0][0]) };
    const uint32_t bl_s[2] = { smem_u32(&Bl[0][0][0]), smem_u32(&Bl[1][0][0]) };

    const int lane_r = lane & 15;          // ldmatrix row within 16-row group
    const int lane_c = (lane >> 4) * 8;    // k-half

    // Staging registers: A 16 fp32, B 2x (8+8) bf16.
    float4 a_reg[4];
    uint4  bh_reg[2], bl_reg[2];

    // ---- load tile 0 into staging ----
    #pragma unroll
    for (int q = 0; q < 4; ++q)
        a_reg[q] = *reinterpret_cast<const float4*>(a_ptr + q * 4);
    bh_reg[0] = *reinterpret_cast<const uint4*>(bh_ptr);
    bh_reg[1] = *reinterpret_cast<const uint4*>(bh_ptr + 8);
    bl_reg[0] = *reinterpret_cast<const uint4*>(bl_ptr);
    bl_reg[1] = *reinterpret_cast<const uint4*>(bl_ptr + 8);

    const int ktiles = K >> 5;

    #pragma unroll 1
    for (int kt = 0; kt < ktiles; ++kt) {
        const int buf = kt & 1;

        // Store staged tile into smem[buf]: split A fp32 -> hi/lo bf16.
        {
            __nv_bfloat16 hh[16], ll[16];
            #pragma unroll
            for (int q = 0; q < 4; ++q) {
                float vv[4] = { a_reg[q].x, a_reg[q].y, a_reg[q].z, a_reg[q].w };
                #pragma unroll
                for (int j = 0; j < 4; ++j) {
                    __nv_bfloat16 h = __float2bfloat16(vv[j]);
                    hh[q * 4 + j] = h;
                    ll[q * 4 + j] = __float2bfloat16(vv[j] - __bfloat162float(h));
                }
            }
            *reinterpret_cast<uint4*>(&Ah[buf][l_row][l_col])     = reinterpret_cast<uint4*>(hh)[0];
            *reinterpret_cast<uint4*>(&Ah[buf][l_row][l_col + 8]) = reinterpret_cast<uint4*>(hh)[1];
            *reinterpret_cast<uint4*>(&Al[buf][l_row][l_col])     = reinterpret_cast<uint4*>(ll)[0];
            *reinterpret_cast<uint4*>(&Al[buf][l_row][l_col + 8]) = reinterpret_cast<uint4*>(ll)[1];
            *reinterpret_cast<uint4*>(&Bh[buf][l_row][l_col])     = bh_reg[0];
            *reinterpret_cast<uint4*>(&Bh[buf][l_row][l_col + 8]) = bh_reg[1];
            *reinterpret_cast<uint4*>(&Bl[buf][l_row][l_col])     = bl_reg[0];
            *reinterpret_cast<uint4*>(&Bl[buf][l_row][l_col + 8]) = bl_reg[1];
        }
        __syncthreads();

        // Prefetch next tile into staging registers (overlaps with MMA below).
        if (kt + 1 < ktiles) {
            const int k0 = (kt + 1) << 5;
            #pragma unroll
            for (int q = 0; q < 4; ++q)
                a_reg[q] = *reinterpret_cast<const float4*>(a_ptr + k0 + q * 4);
            bh_reg[0] = *reinterpret_cast<const uint4*>(bh_ptr + k0);
            bh_reg[1] = *reinterpret_cast<const uint4*>(bh_ptr + k0 + 8);
            bl_reg[0] = *reinterpret_cast<const uint4*>(bl_ptr + k0);
            bl_reg[1] = *reinterpret_cast<const uint4*>(bl_ptr + k0 + 8);
        }

        // Compute on buf.
        #pragma unroll
        for (int ks = 0; ks < 2; ++ks) {
            const uint32_t a_off = (uint32_t)(ks * 16 + lane_c) * 2;

            uint32_t ah[4][4], al[4][4];
            #pragma unroll
            for (int mf = 0; mf < 4; ++mf) {
                const uint32_t ro = (uint32_t)((wm + mf * 16 + lane_r) * LDS) * 2;
                ldsm_x4(ah[mf], ah_s[buf] + ro + a_off);
                ldsm_x4(al[mf], al_s[buf] + ro + a_off);
            }
            uint32_t bh[4][2], bl[4][2];
            #pragma unroll
            for (int np = 0; np < 2; ++np) {
                const uint32_t ro = (uint32_t)((wn + np * 16 + lane_r) * LDS) * 2;
                uint32_t r[4];
                ldsm_x4(r, bh_s[buf] + ro + a_off);
                bh[np * 2 + 0][0] = r[0]; bh[np * 2 + 0][1] = r[2];
                bh[np * 2 + 1][0] = r[1]; bh[np * 2 + 1][1] = r[3];
                ldsm_x4(r, bl_s[buf] + ro + a_off);
                bl[np * 2 + 0][0] = r[0]; bl[np * 2 + 0][1] = r[2];
                bl[np * 2 + 1][0] = r[1]; bl[np * 2 + 1][1] = r[3];
            }

            #pragma unroll
            for (int mf = 0; mf < 4; ++mf)
                #pragma unroll
                for (int nf = 0; nf < 4; ++nf) {
                    mma16816(acc[mf][nf], ah[mf], bh[nf]);
                    mma16816(acc[mf][nf], ah[mf], bl[nf]);
                    mma16816(acc[mf][nf], al[mf], bh[nf]);
                }
        }
        __syncthreads();
    }

    // Epilogue. Thread owns rows (gr, gr+8), cols 2*(lane%4)+{0,1} per fragment.
    const int gr = lane >> 2;
    const int gc = (lane & 3) * 2;
    #pragma unroll
    for (int mf = 0; mf < 4; ++mf) {
        const int row0 = bm + wm + mf * 16 + gr;
        const int row1 = row0 + 8;
        #pragma unroll
        for (int nf = 0; nf < 4; ++nf) {
            const int col = bn + wn + nf * 8 + gc;
            const float bz0 = bias[col], bz1 = bias[col + 1];
            float v00 = acc[mf][nf][0] + bz0, v01 = acc[mf][nf][1] + bz1;
            float v10 = acc[mf][nf][2] + bz0, v11 = acc[mf][nf][3] + bz1;
            if (EPI != 0) {
                v00 = fmaxf(v00, 0.f); v01 = fmaxf(v01, 0.f);
                v10 = fmaxf(v10, 0.f); v11 = fmaxf(v11, 0.f);
            }
            if (row0 < M) {
                float2 v; v.x = v00; v.y = v01;
                *reinterpret_cast<float2*>(out0 + (size_t)row0 * N + col) = v;
                if (EPI == 2)
                    *reinterpret_cast<float2*>(out1 + (size_t)row0 * N + col) = v;
            }
            if (row1 < M) {
                float2 v; v.x = v10; v.y = v11;
                *reinterpret_cast<float2*>(out0 + (size_t)row1 * N + col) = v;
                if (EPI == 2)
                    *reinterpret_cast<float2*>(out1 + (size_t)row1 * N + col) = v;
            }
        }
    }
}

// ---------------------------------------------------------------------------
// Launch
// ---------------------------------------------------------------------------
extern "C" void kernel_launch(void* const* d_in, const int* in_sizes, int n_in,
                              void* d_out, int out_size) {
    const float* x    = (const float*)d_in[0];
    const float* W1a  = (const float*)d_in[1];
    const float* b1a  = (const float*)d_in[2];
    const float* W2a  = (const float*)d_in[3];
    const float* b2a  = (const float*)d_in[4];
    const float* W1b  = (const float*)d_in[5];
    const float* b1b  = (const float*)d_in[6];
    const float* W2b  = (const float*)d_in[7];
    const float* b2b  = (const float*)d_in[8];
    const void*  ei   = d_in[9];

    const int M = N_NODES;
    const int E = in_sizes[9] / 2;

    float *F0, *F1, *F2;
    __nv_bfloat16 *WTH, *WTL;
    cudaGetSymbolAddress((void**)&F0, g_f0);
    cudaGetSymbolAddress((void**)&F1, g_f1);
    cudaGetSymbolAddress((void**)&F2, g_f2);
    cudaGetSymbolAddress((void**)&WTH, g_wthi);
    cudaGetSymbolAddress((void**)&WTL, g_wtlo);

    float* out = (float*)d_out;
    const int GY = M_PAD / 128;   // 391

    detect_idx_kernel<<<1, 1>>>((const long long*)ei);
    prep_weights_all<<<(196608 + 255) / 256, 256>>>(W1a, W2a, W1b, W2b, WTH, WTL);

    // ---- Layer 0 ----
    {
        int n4 = M * 128 / 4;
        copy_f4<<<(n4 + 255) / 256, 256>>>(x, F0, n4);
        long long work = (long long)E * 32;
        scatter_add_kernel<5><<<(int)((work + 255) / 256), 256>>>(x, F0, ei, E);
    }
    // h1 = relu(agg0 @ W1a + b1a)          [50000,128]@[128,256] -> F1
    mma_gemm<1><<<dim3(2, GY), 256>>>(F0, WTH + 0 * 65536, WTL + 0 * 65536,
                                      b1a, F1, nullptr, M, 128, 256);
    // h2 = relu(h1 @ W2a + b2a)            [50000,256]@[256,256] -> F2 and F0
    mma_gemm<2><<<dim3(2, GY), 256>>>(F1, WTH + 1 * 65536, WTL + 1 * 65536,
                                      b2a, F2, F0, M, 256, 256);

    // ---- Layer 1 ----
    {
        long long work = (long long)E * 64;
        scatter_add_kernel<6><<<(int)((work + 255) / 256), 256>>>(F2, F0, ei, E);
    }
    // h3 = relu(agg1 @ W1b + b1b)          [50000,256]@[256,256] -> F1
    mma_gemm<1><<<dim3(2, GY), 256>>>(F0, WTH + 2 * 65536, WTL + 2 * 65536,
                                      b1b, F1, nullptr, M, 256, 256);
    // out = h3 @ W2b + b2b                 [50000,256]@[256,128] -> d_out
    mma_gemm<0><<<dim3(1, GY), 256>>>(F1, WTH + 3 * 65536, WTL + 3 * 65536,
                                      b2b, out, nullptr, M, 256, 128);
}

// round 8
// speedup vs baseline: 1.3349x; 1.3349x over previous
#include <cuda_runtime.h>
#include <cuda_bf16.h>
#include <cstdint>

// ---------------------------------------------------------------------------
// GIN on GB300 (compute_103-portable):
//   aggregation: CSR build (per launch) + warp-per-node gather (no atomics)
//   GEMMs: bf16 error-compensated split on mma.sync tensor cores
//   C = Ahi@Bhi + Ahi@Blo + Alo@Bhi  (fp32 accumulate) ~ fp32 GEMM, ~6e-6
// ---------------------------------------------------------------------------

#define N_NODES 50000
#define M_PAD   50048      // 128 * 391
#define D_MAX   256
#define E_MAX   (1 << 20)

// Static scratch (zero-initialized; padding rows never written -> stay 0).
__device__ float g_f0[(size_t)M_PAD * D_MAX];          // aggregate (gather out)
__device__ float g_f1[(size_t)M_PAD * D_MAX];          // h2 fp32
__device__ __nv_bfloat16 g_ahi[(size_t)M_PAD * D_MAX];
__device__ __nv_bfloat16 g_alo[(size_t)M_PAD * D_MAX];
__device__ __nv_bfloat16 g_bhi[(size_t)M_PAD * D_MAX];
__device__ __nv_bfloat16 g_blo[(size_t)M_PAD * D_MAX];
__device__ __nv_bfloat16 g_wthi[4][256 * 256];         // transposed weights [N][K]
__device__ __nv_bfloat16 g_wtlo[4][256 * 256];
__device__ int g_deg[N_NODES];
__device__ int g_off[N_NODES + 1];
__device__ int g_pos[N_NODES];
__device__ int g_csr[E_MAX];
__device__ int g_idx_is64;

// ---------------------------------------------------------------------------
// PTX helpers (portable: ldmatrix + mma.sync, sm_80+)
// ---------------------------------------------------------------------------
static __device__ __forceinline__ uint32_t smem_u32(const void* p) {
    uint32_t a;
    asm("{ .reg .u64 t; cvta.to.shared.u64 t, %1; cvt.u32.u64 %0, t; }" : "=r"(a) : "l"(p));
    return a;
}

static __device__ __forceinline__ void ldsm_x4(uint32_t* r, uint32_t addr) {
    asm volatile("ldmatrix.sync.aligned.m8n8.x4.shared.b16 {%0,%1,%2,%3}, [%4];"
                 : "=r"(r[0]), "=r"(r[1]), "=r"(r[2]), "=r"(r[3]) : "r"(addr));
}

static __device__ __forceinline__ void mma16816(float* c, const uint32_t* a, const uint32_t* b) {
    asm volatile("mma.sync.aligned.m16n8k16.row.col.f32.bf16.bf16.f32 "
                 "{%0,%1,%2,%3}, {%4,%5,%6,%7}, {%8,%9}, {%0,%1,%2,%3};"
                 : "+f"(c[0]), "+f"(c[1]), "+f"(c[2]), "+f"(c[3])
                 : "r"(a[0]), "r"(a[1]), "r"(a[2]), "r"(a[3]), "r"(b[0]), "r"(b[1]));
}

// Fetch edge endpoint pair (src, dst) for edge e, handling int64/int32 data.
static __device__ __forceinline__ void edge_pair(const void* ei, int e, int E, int& s, int& d) {
    if (g_idx_is64) {
        const long long* p = (const long long*)ei;
        s = (int)p[e];
        d = (int)p[e + E];
    } else {
        const int* p = (const int*)ei;
        s = p[e];
        d = p[e + E];
    }
    s = min(max(s, 0), N_NODES - 1);
    d = min(max(d, 0), N_NODES - 1);
}

// ---------------------------------------------------------------------------
// Small utility kernels
// ---------------------------------------------------------------------------
__global__ void detect_idx_kernel(const long long* __restrict__ ei) {
    if (threadIdx.x == 0 && blockIdx.x == 0) {
        int is64 = 1;
        #pragma unroll 1
        for (int i = 0; i < 64; ++i) {
            long long v = ei[i];
            if (v < 0 || v >= (long long)N_NODES) { is64 = 0; break; }
        }
        g_idx_is64 = is64;
    }
}

// One kernel prepping all 4 weights: W[K,N] fp32 -> Wt_hi/Wt_lo [N,K] bf16.
__global__ void prep_weights_all(const float* __restrict__ W1a, const float* __restrict__ W2a,
                                 const float* __restrict__ W1b, const float* __restrict__ W2b,
                                 __nv_bfloat16* __restrict__ hi, __nv_bfloat16* __restrict__ lo) {
    int i = blockIdx.x * blockDim.x + threadIdx.x;   // 0 .. 196608
    const float* W; int K, N, base, li;
    if (i < 32768)        { W = W1a; K = 128; N = 256; base = 0;          li = i; }
    else if (i < 98304)   { W = W2a; K = 256; N = 256; base = 1 * 65536;  li = i - 32768; }
    else if (i < 163840)  { W = W1b; K = 256; N = 256; base = 2 * 65536;  li = i - 98304; }
    else if (i < 196608)  { W = W2b; K = 256; N = 128; base = 3 * 65536;  li = i - 163840; }
    else return;
    int n = li / K, k = li % K;
    float v = W[(size_t)k * N + n];
    __nv_bfloat16 h = __float2bfloat16(v);
    hi[base + li] = h;
    lo[base + li] = __float2bfloat16(v - __bfloat162float(h));
}

// Split node features fp32 -> hi/lo bf16, zero padding rows.
__global__ void split_feats4(const float4* __restrict__ A,
                             __nv_bfloat16* __restrict__ hi,
                             __nv_bfloat16* __restrict__ lo,
                             int n4_valid, int n4_total) {
    int i = blockIdx.x * blockDim.x + threadIdx.x;
    if (i >= n4_total) return;
    float4 v = (i < n4_valid) ? A[i] : make_float4(0.f, 0.f, 0.f, 0.f);
    __nv_bfloat16 h[4], l[4];
    float vv[4] = {v.x, v.y, v.z, v.w};
    #pragma unroll
    for (int j = 0; j < 4; ++j) {
        h[j] = __float2bfloat16(vv[j]);
        l[j] = __float2bfloat16(vv[j] - __bfloat162float(h[j]));
    }
    *reinterpret_cast<uint2*>(hi + (size_t)i * 4) = *reinterpret_cast<uint2*>(h);
    *reinterpret_cast<uint2*>(lo + (size_t)i * 4) = *reinterpret_cast<uint2*>(l);
}

// ---------------------------------------------------------------------------
// CSR build: zero -> histogram -> scan -> fill (re-run every launch).
// ---------------------------------------------------------------------------
__global__ void zero_deg_kernel(int n) {
    int i = blockIdx.x * blockDim.x + threadIdx.x;
    if (i < n) g_deg[i] = 0;
}

__global__ void hist_kernel(const void* __restrict__ ei, int E) {
    int e = blockIdx.x * blockDim.x + threadIdx.x;
    if (e >= E) return;
    int s, d;
    edge_pair(ei, e, E, s, d);
    atomicAdd(&g_deg[d], 1);
}

// One-block exclusive scan over g_deg (N <= 1024*49). Writes g_off and g_pos.
__global__ __launch_bounds__(1024)
void scan_kernel(int n) {
    __shared__ int sums[1024];
    const int t = threadIdx.x;
    const int CH = (n + 1023) / 1024;
    const int base = t * CH;
    int s = 0;
    for (int j = 0; j < CH; ++j) {
        int idx = base + j;
        if (idx < n) s += g_deg[idx];
    }
    sums[t] = s;
    __syncthreads();
    // Hillis-Steele inclusive scan.
    for (int ofs = 1; ofs < 1024; ofs <<= 1) {
        int v = (t >= ofs) ? sums[t - ofs] : 0;
        __syncthreads();
        sums[t] += v;
        __syncthreads();
    }
    int run = (t > 0) ? sums[t - 1] : 0;
    for (int j = 0; j < CH; ++j) {
        int idx = base + j;
        if (idx < n) {
            g_off[idx] = run;
            g_pos[idx] = run;
            run += g_deg[idx];
        }
    }
    if (t == 1023) g_off[n] = sums[1023];
}

__global__ void fill_kernel(const void* __restrict__ ei, int E) {
    int e = blockIdx.x * blockDim.x + threadIdx.x;
    if (e >= E) return;
    int s, d;
    edge_pair(ei, e, E, s, d);
    int slot = atomicAdd(&g_pos[d], 1);
    g_csr[slot] = s;
}

// ---------------------------------------------------------------------------
// Gather: out[i] = feat[i] + sum_{j in N(i)} feat[j].  One warp per node.
// VEC = float4 chunks per lane (1 -> D=128, 2 -> D=256).
// ---------------------------------------------------------------------------
template<int VEC>
__global__ void gather_kernel(const float* __restrict__ feat,
                              float* __restrict__ out, int n) {
    const int D = VEC * 128;
    int w = (blockIdx.x * blockDim.x + threadIdx.x) >> 5;
    const int lane = threadIdx.x & 31;
    if (w >= n) return;

    const int beg = g_off[w];
    const int end = g_off[w + 1];

    float4 acc[VEC];
    #pragma unroll
    for (int v = 0; v < VEC; ++v)
        acc[v] = *reinterpret_cast<const float4*>(feat + (size_t)w * D + v * 128 + lane * 4);

    int i = beg;
    // Unroll by 2 for MLP.
    for (; i + 1 < end; i += 2) {
        int s0 = g_csr[i];
        int s1 = g_csr[i + 1];
        #pragma unroll
        for (int v = 0; v < VEC; ++v) {
            float4 a = *reinterpret_cast<const float4*>(feat + (size_t)s0 * D + v * 128 + lane * 4);
            float4 b = *reinterpret_cast<const float4*>(feat + (size_t)s1 * D + v * 128 + lane * 4);
            acc[v].x += a.x + b.x;
            acc[v].y += a.y + b.y;
            acc[v].z += a.z + b.z;
            acc[v].w += a.w + b.w;
        }
    }
    if (i < end) {
        int s0 = g_csr[i];
        #pragma unroll
        for (int v = 0; v < VEC; ++v) {
            float4 a = *reinterpret_cast<const float4*>(feat + (size_t)s0 * D + v * 128 + lane * 4);
            acc[v].x += a.x;
            acc[v].y += a.y;
            acc[v].z += a.z;
            acc[v].w += a.w;
        }
    }

    #pragma unroll
    for (int v = 0; v < VEC; ++v)
        *reinterpret_cast<float4*>(out + (size_t)w * D + v * 128 + lane * 4) = acc[v];
}

// ---------------------------------------------------------------------------
// mma.sync GEMM (R5-proven shape): C[M,N] = A[M,K]@B^T (B transposed [N,K]).
// A,B as bf16 hi/lo splits; fp32 accumulate of 3 split products.
// CTA tile 128x128, BK=32, 256 threads (8 warps, 2x4), warp tile 64x32.
// EPI: 0 = fp32 out (no relu), 1 = relu -> bf16 hi/lo split, 2 = relu -> fp32.
// ---------------------------------------------------------------------------
template<int EPI>
__global__ __launch_bounds__(256)
void mma_gemm(const __nv_bfloat16* __restrict__ Ahi, const __nv_bfloat16* __restrict__ Alo,
              const __nv_bfloat16* __restrict__ Bth, const __nv_bfloat16* __restrict__ Btl,
              const float* __restrict__ bias,
              float* __restrict__ outf,
              __nv_bfloat16* __restrict__ ohi, __nv_bfloat16* __restrict__ olo,
              int M, int K, int N) {
    constexpr int BM = 128, BK = 32, LDS = BK + 8;   // pad -> conflict-free ldmatrix
    __shared__ __nv_bfloat16 As[2][BM][LDS];
    __shared__ __nv_bfloat16 Bs[2][BM][LDS];

    const int tid  = threadIdx.x;
    const int wid  = tid >> 5;
    const int lane = tid & 31;
    const int bm = blockIdx.y * 128;
    const int bn = blockIdx.x * 128;

    const int wm = (wid >> 2) * 64;   // warp m offset: 0 or 64
    const int wn = (wid & 3) * 32;    // warp n offset: 0,32,64,96

    const uint32_t as0 = smem_u32(&As[0][0][0]);
    const uint32_t as1 = smem_u32(&As[1][0][0]);
    const uint32_t bs0 = smem_u32(&Bs[0][0][0]);
    const uint32_t bs1 = smem_u32(&Bs[1][0][0]);

    const int lane_r = lane & 15;          // ldmatrix row within 16-row group
    const int lane_c = (lane >> 4) * 8;    // k-half

    float acc[4][4][4];
    #pragma unroll
    for (int mf = 0; mf < 4; ++mf)
        #pragma unroll
        for (int nf = 0; nf < 4; ++nf)
            #pragma unroll
            for (int c = 0; c < 4; ++c)
                acc[mf][nf][c] = 0.0f;

    // Global load mapping: 512 chunks of 8 bf16 per tile (2 iters x 256 thr).
    const int g_row0 = tid >> 2;                 // 0..63
    const int g_col  = (tid & 3) * 8;            // 0,8,16,24

    const int ktiles = K >> 5;
    for (int kt = 0; kt < ktiles; ++kt) {
        const int k0 = kt << 5;
        #pragma unroll
        for (int it = 0; it < 2; ++it) {
            const int row = g_row0 + it * 64;
            const size_t ga = (size_t)(bm + row) * K + k0 + g_col;
            const size_t gb = (size_t)(bn + row) * K + k0 + g_col;
            *reinterpret_cast<uint4*>(&As[0][row][g_col]) = *reinterpret_cast<const uint4*>(Ahi + ga);
            *reinterpret_cast<uint4*>(&As[1][row][g_col]) = *reinterpret_cast<const uint4*>(Alo + ga);
            *reinterpret_cast<uint4*>(&Bs[0][row][g_col]) = *reinterpret_cast<const uint4*>(Bth + gb);
            *reinterpret_cast<uint4*>(&Bs[1][row][g_col]) = *reinterpret_cast<const uint4*>(Btl + gb);
        }
        __syncthreads();

        #pragma unroll
        for (int ks = 0; ks < 2; ++ks) {
            const int kb = ks * 16;
            const uint32_t a_off = (uint32_t)(kb + lane_c) * 2;

            uint32_t ah[4][4], al[4][4];
            #pragma unroll
            for (int mf = 0; mf < 4; ++mf) {
                const uint32_t ro = (uint32_t)((wm + mf * 16 + lane_r) * LDS) * 2;
                ldsm_x4(ah[mf], as0 + ro + a_off);
                ldsm_x4(al[mf], as1 + ro + a_off);
            }
            uint32_t bh[4][2], bl[4][2];
            #pragma unroll
            for (int np = 0; np < 2; ++np) {     // n-frag pairs
                const uint32_t ro = (uint32_t)((wn + np * 16 + lane_r) * LDS) * 2;
                uint32_t r[4];
                ldsm_x4(r, bs0 + ro + a_off);
                bh[np * 2 + 0][0] = r[0]; bh[np * 2 + 0][1] = r[2];
                bh[np * 2 + 1][0] = r[1]; bh[np * 2 + 1][1] = r[3];
                ldsm_x4(r, bs1 + ro + a_off);
                bl[np * 2 + 0][0] = r[0]; bl[np * 2 + 0][1] = r[2];
                bl[np * 2 + 1][0] = r[1]; bl[np * 2 + 1][1] = r[3];
            }

            #pragma unroll
            for (int mf = 0; mf < 4; ++mf)
                #pragma unroll
                for (int nf = 0; nf < 4; ++nf) {
                    mma16816(acc[mf][nf], ah[mf], bh[nf]);
                    mma16816(acc[mf][nf], ah[mf], bl[nf]);
                    mma16816(acc[mf][nf], al[mf], bh[nf]);
                }
        }
        __syncthreads();
    }

    // Epilogue. Thread owns rows (gr, gr+8), cols 2*(lane%4)+{0,1} per fragment.
    const int gr = lane >> 2;
    const int gc = (lane & 3) * 2;
    #pragma unroll
    for (int mf = 0; mf < 4; ++mf) {
        const int row0 = bm + wm + mf * 16 + gr;
        const int row1 = row0 + 8;
        #pragma unroll
        for (int nf = 0; nf < 4; ++nf) {
            const int col = bn + wn + nf * 8 + gc;
            const float bz0 = bias[col], bz1 = bias[col + 1];
            float v00 = acc[mf][nf][0] + bz0, v01 = acc[mf][nf][1] + bz1;
            float v10 = acc[mf][nf][2] + bz0, v11 = acc[mf][nf][3] + bz1;
            if (EPI != 0) {
                v00 = fmaxf(v00, 0.f); v01 = fmaxf(v01, 0.f);
                v10 = fmaxf(v10, 0.f); v11 = fmaxf(v11, 0.f);
            }
            if (EPI == 1) {
                if (row0 < M) {
                    __nv_bfloat16 h0 = __float2bfloat16(v00), h1 = __float2bfloat16(v01);
                    __nv_bfloat162 hh; hh.x = h0; hh.y = h1;
                    __nv_bfloat162 ll;
                    ll.x = __float2bfloat16(v00 - __bfloat162float(h0));
                    ll.y = __float2bfloat16(v01 - __bfloat162float(h1));
                    *reinterpret_cast<__nv_bfloat162*>(ohi + (size_t)row0 * N + col) = hh;
                    *reinterpret_cast<__nv_bfloat162*>(olo + (size_t)row0 * N + col) = ll;
                }
                if (row1 < M) {
                    __nv_bfloat16 h0 = __float2bfloat16(v10), h1 = __float2bfloat16(v11);
                    __nv_bfloat162 hh; hh.x = h0; hh.y = h1;
                    __nv_bfloat162 ll;
                    ll.x = __float2bfloat16(v10 - __bfloat162float(h0));
                    ll.y = __float2bfloat16(v11 - __bfloat162float(h1));
                    *reinterpret_cast<__nv_bfloat162*>(ohi + (size_t)row1 * N + col) = hh;
                    *reinterpret_cast<__nv_bfloat162*>(olo + (size_t)row1 * N + col) = ll;
                }
            } else {
                if (row0 < M) {
                    float2 v; v.x = v00; v.y = v01;
                    *reinterpret_cast<float2*>(outf + (size_t)row0 * N + col) = v;
                }
                if (row1 < M) {
                    float2 v; v.x = v10; v.y = v11;
                    *reinterpret_cast<float2*>(outf + (size_t)row1 * N + col) = v;
                }
            }
        }
    }
}

// ---------------------------------------------------------------------------
// Launch
// ---------------------------------------------------------------------------
extern "C" void kernel_launch(void* const* d_in, const int* in_sizes, int n_in,
                              void* d_out, int out_size) {
    const float* x    = (const float*)d_in[0];
    const float* W1a  = (const float*)d_in[1];
    const float* b1a  = (const float*)d_in[2];
    const float* W2a  = (const float*)d_in[3];
    const float* b2a  = (const float*)d_in[4];
    const float* W1b  = (const float*)d_in[5];
    const float* b1b  = (const float*)d_in[6];
    const float* W2b  = (const float*)d_in[7];
    const float* b2b  = (const float*)d_in[8];
    const void*  ei   = d_in[9];

    const int M = N_NODES;
    const int E = in_sizes[9] / 2;

    float *F0, *F1;
    __nv_bfloat16 *AHI, *ALO, *BHI, *BLO, *WTH, *WTL;
    cudaGetSymbolAddress((void**)&F0, g_f0);
    cudaGetSymbolAddress((void**)&F1, g_f1);
    cudaGetSymbolAddress((void**)&AHI, g_ahi);
    cudaGetSymbolAddress((void**)&ALO, g_alo);
    cudaGetSymbolAddress((void**)&BHI, g_bhi);
    cudaGetSymbolAddress((void**)&BLO, g_blo);
    cudaGetSymbolAddress((void**)&WTH, g_wthi);
    cudaGetSymbolAddress((void**)&WTL, g_wtlo);

    float* out = (float*)d_out;
    const int GY = M_PAD / 128;   // 391

    // Index dtype + weight prep + CSR build (shared by both layers).
    detect_idx_kernel<<<1, 1>>>((const long long*)ei);
    prep_weights_all<<<(196608 + 255) / 256, 256>>>(W1a, W2a, W1b, W2b, WTH, WTL);
    zero_deg_kernel<<<(N_NODES + 255) / 256, 256>>>(N_NODES);
    hist_kernel<<<(E + 255) / 256, 256>>>(ei, E);
    scan_kernel<<<1, 1024>>>(N_NODES);
    fill_kernel<<<(E + 255) / 256, 256>>>(ei, E);

    // ---- Layer 0 ----
    // F0 = x + gather(x)   (self term fused; no copy, no atomics)
    gather_kernel<1><<<(M * 32 + 255) / 256, 256>>>(x, F0, M);
    split_feats4<<<(M_PAD * 128 / 4 + 255) / 256, 256>>>((const float4*)F0, AHI, ALO,
                                                         M * 128 / 4, M_PAD * 128 / 4);
    // h1 = relu(F0 @ W1a + b1a) -> split     [50000,128]@[128,256]
    mma_gemm<1><<<dim3(2, GY), 256>>>(AHI, ALO, WTH + 0 * 65536, WTL + 0 * 65536,
                                      b1a, nullptr, BHI, BLO, M, 128, 256);
    // h2 = relu(h1 @ W2a + b2a) -> fp32 F1   [50000,256]@[256,256]
    mma_gemm<2><<<dim3(2, GY), 256>>>(BHI, BLO, WTH + 1 * 65536, WTL + 1 * 65536,
                                      b2a, F1, nullptr, nullptr, M, 256, 256);

    // ---- Layer 1 ----
    // F0 = h2 + gather(h2)
    gather_kernel<2><<<(M * 32 + 255) / 256, 256>>>(F1, F0, M);
    split_feats4<<<(M_PAD * 256 / 4 + 255) / 256, 256>>>((const float4*)F0, AHI, ALO,
                                                         M * 256 / 4, M_PAD * 256 / 4);
    // h3 = relu(F0 @ W1b + b1b) -> split     [50000,256]@[256,256]
    mma_gemm<1><<<dim3(2, GY), 256>>>(AHI, ALO, WTH + 2 * 65536, WTL + 2 * 65536,
                                      b1b, nullptr, BHI, BLO, M, 256, 256);
    // out = h3 @ W2b + b2b                   [50000,256]@[256,128]
    mma_gemm<0><<<dim3(1, GY), 256>>>(BHI, BLO, WTH + 3 * 65536, WTL + 3 * 65536,
                                      b2b, out, nullptr, nullptr, M, 256, 128);
}

// round 9
// speedup vs baseline: 1.3900x; 1.0413x over previous
#include <cuda_runtime.h>
#include <cuda_bf16.h>
#include <cstdint>

// ---------------------------------------------------------------------------
// GIN on GB300 (compute_103-portable):
//   aggregation: CSR build (per launch) + warp-per-node gather (no atomics),
//                gather emits bf16 hi/lo split directly (no fp32 staging)
//   GEMMs: bf16 error-compensated split on mma.sync tensor cores
//   C = Ahi@Bhi + Ahi@Blo + Alo@Bhi  (fp32 accumulate) ~ fp32 GEMM, ~6e-6
// ---------------------------------------------------------------------------

#define N_NODES 50000
#define M_PAD   50048      // 128 * 391
#define D_MAX   256
#define E_MAX   (1 << 20)

// Static scratch. Padding rows of AHI/ALO/BHI/BLO may hold stale data; they
// only influence GEMM output rows >= N_NODES, which are never stored.
__device__ float g_f1[(size_t)M_PAD * D_MAX];          // h2 fp32 (gather input)
__device__ __nv_bfloat16 g_ahi[(size_t)M_PAD * D_MAX];
__device__ __nv_bfloat16 g_alo[(size_t)M_PAD * D_MAX];
__device__ __nv_bfloat16 g_bhi[(size_t)M_PAD * D_MAX];
__device__ __nv_bfloat16 g_blo[(size_t)M_PAD * D_MAX];
__device__ __nv_bfloat16 g_wthi[4][256 * 256];         // transposed weights [N][K]
__device__ __nv_bfloat16 g_wtlo[4][256 * 256];
__device__ int g_deg[N_NODES];
__device__ int g_off[N_NODES + 1];
__device__ int g_pos[N_NODES];
__device__ int g_csr[E_MAX];
__device__ int g_idx_is64;

// ---------------------------------------------------------------------------
// PTX helpers (portable: ldmatrix + mma.sync, sm_80+)
// ---------------------------------------------------------------------------
static __device__ __forceinline__ uint32_t smem_u32(const void* p) {
    uint32_t a;
    asm("{ .reg .u64 t; cvta.to.shared.u64 t, %1; cvt.u32.u64 %0, t; }" : "=r"(a) : "l"(p));
    return a;
}

static __device__ __forceinline__ void ldsm_x4(uint32_t* r, uint32_t addr) {
    asm volatile("ldmatrix.sync.aligned.m8n8.x4.shared.b16 {%0,%1,%2,%3}, [%4];"
                 : "=r"(r[0]), "=r"(r[1]), "=r"(r[2]), "=r"(r[3]) : "r"(addr));
}

static __device__ __forceinline__ void mma16816(float* c, const uint32_t* a, const uint32_t* b) {
    asm volatile("mma.sync.aligned.m16n8k16.row.col.f32.bf16.bf16.f32 "
                 "{%0,%1,%2,%3}, {%4,%5,%6,%7}, {%8,%9}, {%0,%1,%2,%3};"
                 : "+f"(c[0]), "+f"(c[1]), "+f"(c[2]), "+f"(c[3])
                 : "r"(a[0]), "r"(a[1]), "r"(a[2]), "r"(a[3]), "r"(b[0]), "r"(b[1]));
}

// Fetch edge endpoint pair (src, dst) for edge e, handling int64/int32 data.
static __device__ __forceinline__ void edge_pair(const void* ei, int e, int E, int& s, int& d) {
    if (g_idx_is64) {
        const long long* p = (const long long*)ei;
        s = (int)p[e];
        d = (int)p[e + E];
    } else {
        const int* p = (const int*)ei;
        s = p[e];
        d = p[e + E];
    }
    s = min(max(s, 0), N_NODES - 1);
    d = min(max(d, 0), N_NODES - 1);
}

// ---------------------------------------------------------------------------
// Small utility kernels
// ---------------------------------------------------------------------------
__global__ void detect_idx_kernel(const long long* __restrict__ ei) {
    if (threadIdx.x == 0 && blockIdx.x == 0) {
        int is64 = 1;
        #pragma unroll 1
        for (int i = 0; i < 64; ++i) {
            long long v = ei[i];
            if (v < 0 || v >= (long long)N_NODES) { is64 = 0; break; }
        }
        g_idx_is64 = is64;
    }
}

// One kernel prepping all 4 weights: W[K,N] fp32 -> Wt_hi/Wt_lo [N,K] bf16.
__global__ void prep_weights_all(const float* __restrict__ W1a, const float* __restrict__ W2a,
                                 const float* __restrict__ W1b, const float* __restrict__ W2b,
                                 __nv_bfloat16* __restrict__ hi, __nv_bfloat16* __restrict__ lo) {
    int i = blockIdx.x * blockDim.x + threadIdx.x;   // 0 .. 196608
    const float* W; int K, N, base, li;
    if (i < 32768)        { W = W1a; K = 128; N = 256; base = 0;          li = i; }
    else if (i < 98304)   { W = W2a; K = 256; N = 256; base = 1 * 65536;  li = i - 32768; }
    else if (i < 163840)  { W = W1b; K = 256; N = 256; base = 2 * 65536;  li = i - 98304; }
    else if (i < 196608)  { W = W2b; K = 256; N = 128; base = 3 * 65536;  li = i - 163840; }
    else return;
    int n = li / K, k = li % K;
    float v = W[(size_t)k * N + n];
    __nv_bfloat16 h = __float2bfloat16(v);
    hi[base + li] = h;
    lo[base + li] = __float2bfloat16(v - __bfloat162float(h));
}

// ---------------------------------------------------------------------------
// CSR build: zero -> histogram -> scan -> fill (re-run every launch).
// ---------------------------------------------------------------------------
__global__ void zero_deg_kernel(int n) {
    int i = blockIdx.x * blockDim.x + threadIdx.x;
    if (i < n) g_deg[i] = 0;
}

__global__ void hist_kernel(const void* __restrict__ ei, int E) {
    int e = blockIdx.x * blockDim.x + threadIdx.x;
    if (e >= E) return;
    int s, d;
    edge_pair(ei, e, E, s, d);
    atomicAdd(&g_deg[d], 1);
}

// One-block exclusive scan over g_deg. Writes g_off and g_pos.
__global__ __launch_bounds__(1024)
void scan_kernel(int n) {
    __shared__ int sums[1024];
    const int t = threadIdx.x;
    const int CH = (n + 1023) / 1024;
    const int base = t * CH;
    int s = 0;
    for (int j = 0; j < CH; ++j) {
        int idx = base + j;
        if (idx < n) s += g_deg[idx];
    }
    sums[t] = s;
    __syncthreads();
    for (int ofs = 1; ofs < 1024; ofs <<= 1) {
        int v = (t >= ofs) ? sums[t - ofs] : 0;
        __syncthreads();
        sums[t] += v;
        __syncthreads();
    }
    int run = (t > 0) ? sums[t - 1] : 0;
    for (int j = 0; j < CH; ++j) {
        int idx = base + j;
        if (idx < n) {
            g_off[idx] = run;
            g_pos[idx] = run;
            run += g_deg[idx];
        }
    }
    if (t == 1023) g_off[n] = sums[1023];
}

__global__ void fill_kernel(const void* __restrict__ ei, int E) {
    int e = blockIdx.x * blockDim.x + threadIdx.x;
    if (e >= E) return;
    int s, d;
    edge_pair(ei, e, E, s, d);
    int slot = atomicAdd(&g_pos[d], 1);
    g_csr[slot] = s;
}

// ---------------------------------------------------------------------------
// Gather + split: acc[i] = feat[i] + sum_{j in N(i)} feat[j]  (fp32),
// then emit bf16 hi/lo pair directly. One warp per node.
// VEC = float4 chunks per lane (1 -> D=128, 2 -> D=256).
// ---------------------------------------------------------------------------
template<int VEC>
__global__ void gather_split_kernel(const float* __restrict__ feat,
                                    __nv_bfloat16* __restrict__ hi,
                                    __nv_bfloat16* __restrict__ lo, int n) {
    const int D = VEC * 128;
    int w = (blockIdx.x * blockDim.x + threadIdx.x) >> 5;
    const int lane = threadIdx.x & 31;
    if (w >= n) return;

    const int beg = g_off[w];
    const int end = g_off[w + 1];

    float4 acc[VEC];
    #pragma unroll
    for (int v = 0; v < VEC; ++v)
        acc[v] = *reinterpret_cast<const float4*>(feat + (size_t)w * D + v * 128 + lane * 4);

    int i = beg;
    for (; i + 1 < end; i += 2) {
        int s0 = g_csr[i];
        int s1 = g_csr[i + 1];
        #pragma unroll
        for (int v = 0; v < VEC; ++v) {
            float4 a = *reinterpret_cast<const float4*>(feat + (size_t)s0 * D + v * 128 + lane * 4);
            float4 b = *reinterpret_cast<const float4*>(feat + (size_t)s1 * D + v * 128 + lane * 4);
            acc[v].x += a.x + b.x;
            acc[v].y += a.y + b.y;
            acc[v].z += a.z + b.z;
            acc[v].w += a.w + b.w;
        }
    }
    if (i < end) {
        int s0 = g_csr[i];
        #pragma unroll
        for (int v = 0; v < VEC; ++v) {
            float4 a = *reinterpret_cast<const float4*>(feat + (size_t)s0 * D + v * 128 + lane * 4);
            acc[v].x += a.x;
            acc[v].y += a.y;
            acc[v].z += a.z;
            acc[v].w += a.w;
        }
    }

    #pragma unroll
    for (int v = 0; v < VEC; ++v) {
        float vv[4] = { acc[v].x, acc[v].y, acc[v].z, acc[v].w };
        __nv_bfloat16 h[4], l[4];
        #pragma unroll
        for (int j = 0; j < 4; ++j) {
            h[j] = __float2bfloat16(vv[j]);
            l[j] = __float2bfloat16(vv[j] - __bfloat162float(h[j]));
        }
        *reinterpret_cast<uint2*>(hi + (size_t)w * D + v * 128 + lane * 4) =
            *reinterpret_cast<uint2*>(h);
        *reinterpret_cast<uint2*>(lo + (size_t)w * D + v * 128 + lane * 4) =
            *reinterpret_cast<uint2*>(l);
    }
}

// ---------------------------------------------------------------------------
// mma.sync GEMM (R5-proven shape): C[M,N] = A[M,K]@B^T (B transposed [N,K]).
// A,B as bf16 hi/lo splits; fp32 accumulate of 3 split products.
// CTA tile 128x128, BK=32, 256 threads (8 warps, 2x4), warp tile 64x32.
// EPI: 0 = fp32 out (no relu), 1 = relu -> bf16 hi/lo split, 2 = relu -> fp32.
// ---------------------------------------------------------------------------
template<int EPI>
__global__ __launch_bounds__(256)
void mma_gemm(const __nv_bfloat16* __restrict__ Ahi, const __nv_bfloat16* __restrict__ Alo,
              const __nv_bfloat16* __restrict__ Bth, const __nv_bfloat16* __restrict__ Btl,
              const float* __restrict__ bias,
              float* __restrict__ outf,
              __nv_bfloat16* __restrict__ ohi, __nv_bfloat16* __restrict__ olo,
              int M, int K, int N) {
    constexpr int BM = 128, BK = 32, LDS = BK + 8;   // pad -> conflict-free ldmatrix
    __shared__ __nv_bfloat16 As[2][BM][LDS];
    __shared__ __nv_bfloat16 Bs[2][BM][LDS];

    const int tid  = threadIdx.x;
    const int wid  = tid >> 5;
    const int lane = tid & 31;
    const int bm = blockIdx.y * 128;
    const int bn = blockIdx.x * 128;

    const int wm = (wid >> 2) * 64;   // warp m offset: 0 or 64
    const int wn = (wid & 3) * 32;    // warp n offset: 0,32,64,96

    const uint32_t as0 = smem_u32(&As[0][0][0]);
    const uint32_t as1 = smem_u32(&As[1][0][0]);
    const uint32_t bs0 = smem_u32(&Bs[0][0][0]);
    const uint32_t bs1 = smem_u32(&Bs[1][0][0]);

    const int lane_r = lane & 15;          // ldmatrix row within 16-row group
    const int lane_c = (lane >> 4) * 8;    // k-half

    float acc[4][4][4];
    #pragma unroll
    for (int mf = 0; mf < 4; ++mf)
        #pragma unroll
        for (int nf = 0; nf < 4; ++nf)
            #pragma unroll
            for (int c = 0; c < 4; ++c)
                acc[mf][nf][c] = 0.0f;

    // Global load mapping: 512 chunks of 8 bf16 per tile (2 iters x 256 thr).
    const int g_row0 = tid >> 2;                 // 0..63
    const int g_col  = (tid & 3) * 8;            // 0,8,16,24

    const int ktiles = K >> 5;
    for (int kt = 0; kt < ktiles; ++kt) {
        const int k0 = kt << 5;
        #pragma unroll
        for (int it = 0; it < 2; ++it) {
            const int row = g_row0 + it * 64;
            const size_t ga = (size_t)(bm + row) * K + k0 + g_col;
            const size_t gb = (size_t)(bn + row) * K + k0 + g_col;
            *reinterpret_cast<uint4*>(&As[0][row][g_col]) = *reinterpret_cast<const uint4*>(Ahi + ga);
            *reinterpret_cast<uint4*>(&As[1][row][g_col]) = *reinterpret_cast<const uint4*>(Alo + ga);
            *reinterpret_cast<uint4*>(&Bs[0][row][g_col]) = *reinterpret_cast<const uint4*>(Bth + gb);
            *reinterpret_cast<uint4*>(&Bs[1][row][g_col]) = *reinterpret_cast<const uint4*>(Btl + gb);
        }
        __syncthreads();

        #pragma unroll
        for (int ks = 0; ks < 2; ++ks) {
            const int kb = ks * 16;
            const uint32_t a_off = (uint32_t)(kb + lane_c) * 2;

            uint32_t ah[4][4], al[4][4];
            #pragma unroll
            for (int mf = 0; mf < 4; ++mf) {
                const uint32_t ro = (uint32_t)((wm + mf * 16 + lane_r) * LDS) * 2;
                ldsm_x4(ah[mf], as0 + ro + a_off);
                ldsm_x4(al[mf], as1 + ro + a_off);
            }
            uint32_t bh[4][2], bl[4][2];
            #pragma unroll
            for (int np = 0; np < 2; ++np) {     // n-frag pairs
                const uint32_t ro = (uint32_t)((wn + np * 16 + lane_r) * LDS) * 2;
                uint32_t r[4];
                ldsm_x4(r, bs0 + ro + a_off);
                bh[np * 2 + 0][0] = r[0]; bh[np * 2 + 0][1] = r[2];
                bh[np * 2 + 1][0] = r[1]; bh[np * 2 + 1][1] = r[3];
                ldsm_x4(r, bs1 + ro + a_off);
                bl[np * 2 + 0][0] = r[0]; bl[np * 2 + 0][1] = r[2];
                bl[np * 2 + 1][0] = r[1]; bl[np * 2 + 1][1] = r[3];
            }

            #pragma unroll
            for (int mf = 0; mf < 4; ++mf)
                #pragma unroll
                for (int nf = 0; nf < 4; ++nf) {
                    mma16816(acc[mf][nf], ah[mf], bh[nf]);
                    mma16816(acc[mf][nf], ah[mf], bl[nf]);
                    mma16816(acc[mf][nf], al[mf], bh[nf]);
                }
        }
        __syncthreads();
    }

    // Epilogue. Thread owns rows (gr, gr+8), cols 2*(lane%4)+{0,1} per fragment.
    const int gr = lane >> 2;
    const int gc = (lane & 3) * 2;
    #pragma unroll
    for (int mf = 0; mf < 4; ++mf) {
        const int row0 = bm + wm + mf * 16 + gr;
        const int row1 = row0 + 8;
        #pragma unroll
        for (int nf = 0; nf < 4; ++nf) {
            const int col = bn + wn + nf * 8 + gc;
            const float bz0 = bias[col], bz1 = bias[col + 1];
            float v00 = acc[mf][nf][0] + bz0, v01 = acc[mf][nf][1] + bz1;
            float v10 = acc[mf][nf][2] + bz0, v11 = acc[mf][nf][3] + bz1;
            if (EPI != 0) {
                v00 = fmaxf(v00, 0.f); v01 = fmaxf(v01, 0.f);
                v10 = fmaxf(v10, 0.f); v11 = fmaxf(v11, 0.f);
            }
            if (EPI == 1) {
                if (row0 < M) {
                    __nv_bfloat16 h0 = __float2bfloat16(v00), h1 = __float2bfloat16(v01);
                    __nv_bfloat162 hh; hh.x = h0; hh.y = h1;
                    __nv_bfloat162 ll;
                    ll.x = __float2bfloat16(v00 - __bfloat162float(h0));
                    ll.y = __float2bfloat16(v01 - __bfloat162float(h1));
                    *reinterpret_cast<__nv_bfloat162*>(ohi + (size_t)row0 * N + col) = hh;
                    *reinterpret_cast<__nv_bfloat162*>(olo + (size_t)row0 * N + col) = ll;
                }
                if (row1 < M) {
                    __nv_bfloat16 h0 = __float2bfloat16(v10), h1 = __float2bfloat16(v11);
                    __nv_bfloat162 hh; hh.x = h0; hh.y = h1;
                    __nv_bfloat162 ll;
                    ll.x = __float2bfloat16(v10 - __bfloat162float(h0));
                    ll.y = __float2bfloat16(v11 - __bfloat162float(h1));
                    *reinterpret_cast<__nv_bfloat162*>(ohi + (size_t)row1 * N + col) = hh;
                    *reinterpret_cast<__nv_bfloat162*>(olo + (size_t)row1 * N + col) = ll;
                }
            } else {
                if (row0 < M) {
                    float2 v; v.x = v00; v.y = v01;
                    *reinterpret_cast<float2*>(outf + (size_t)row0 * N + col) = v;
                }
                if (row1 < M) {
                    float2 v; v.x = v10; v.y = v11;
                    *reinterpret_cast<float2*>(outf + (size_t)row1 * N + col) = v;
                }
            }
        }
    }
}

// ---------------------------------------------------------------------------
// Launch
// ---------------------------------------------------------------------------
extern "C" void kernel_launch(void* const* d_in, const int* in_sizes, int n_in,
                              void* d_out, int out_size) {
    const float* x    = (const float*)d_in[0];
    const float* W1a  = (const float*)d_in[1];
    const float* b1a  = (const float*)d_in[2];
    const float* W2a  = (const float*)d_in[3];
    const float* b2a  = (const float*)d_in[4];
    const float* W1b  = (const float*)d_in[5];
    const float* b1b  = (const float*)d_in[6];
    const float* W2b  = (const float*)d_in[7];
    const float* b2b  = (const float*)d_in[8];
    const void*  ei   = d_in[9];

    const int M = N_NODES;
    const int E = in_sizes[9] / 2;

    float *F1;
    __nv_bfloat16 *AHI, *ALO, *BHI, *BLO, *WTH, *WTL;
    cudaGetSymbolAddress((void**)&F1, g_f1);
    cudaGetSymbolAddress((void**)&AHI, g_ahi);
    cudaGetSymbolAddress((void**)&ALO, g_alo);
    cudaGetSymbolAddress((void**)&BHI, g_bhi);
    cudaGetSymbolAddress((void**)&BLO, g_blo);
    cudaGetSymbolAddress((void**)&WTH, g_wthi);
    cudaGetSymbolAddress((void**)&WTL, g_wtlo);

    float* out = (float*)d_out;
    const int GY = M_PAD / 128;   // 391

    // Index dtype + weight prep + CSR build (shared by both layers).
    detect_idx_kernel<<<1, 1>>>((const long long*)ei);
    prep_weights_all<<<(196608 + 255) / 256, 256>>>(W1a, W2a, W1b, W2b, WTH, WTL);
    zero_deg_kernel<<<(N_NODES + 255) / 256, 256>>>(N_NODES);
    hist_kernel<<<(E + 255) / 256, 256>>>(ei, E);
    scan_kernel<<<1, 1024>>>(N_NODES);
    fill_kernel<<<(E + 255) / 256, 256>>>(ei, E);

    // ---- Layer 0 ----
    // AHI/ALO = split(x + gather(x))   (self term fused; no staging buffer)
    gather_split_kernel<1><<<(M * 32 + 255) / 256, 256>>>(x, AHI, ALO, M);
    // h1 = relu(agg0 @ W1a + b1a) -> split    [50000,128]@[128,256]
    mma_gemm<1><<<dim3(2, GY), 256>>>(AHI, ALO, WTH + 0 * 65536, WTL + 0 * 65536,
                                      b1a, nullptr, BHI, BLO, M, 128, 256);
    // h2 = relu(h1 @ W2a + b2a) -> fp32 F1    [50000,256]@[256,256]
    mma_gemm<2><<<dim3(2, GY), 256>>>(BHI, BLO, WTH + 1 * 65536, WTL + 1 * 65536,
                                      b2a, F1, nullptr, nullptr, M, 256, 256);

    // ---- Layer 1 ----
    // AHI/ALO = split(h2 + gather(h2))
    gather_split_kernel<2><<<(M * 32 + 255) / 256, 256>>>(F1, AHI, ALO, M);
    // h3 = relu(agg1 @ W1b + b1b) -> split    [50000,256]@[256,256]
    mma_gemm<1><<<dim3(2, GY), 256>>>(AHI, ALO, WTH + 2 * 65536, WTL + 2 * 65536,
                                      b1b, nullptr, BHI, BLO, M, 256, 256);
    // out = h3 @ W2b + b2b                    [50000,256]@[256,128]
    mma_gemm<0><<<dim3(1, GY), 256>>>(BHI, BLO, WTH + 3 * 65536, WTL + 3 * 65536,
                                      b2b, out, nullptr, nullptr, M, 256, 128);
}

// round 10
// speedup vs baseline: 1.4439x; 1.0387x over previous
#include <cuda_runtime.h>
#include <cuda_bf16.h>
#include <cstdint>

// ---------------------------------------------------------------------------
// GIN on GB300 (compute_103-portable):
//   aggregation: CSR build (per launch) + warp-per-node gather (no atomics),
//                gather emits bf16 hi/lo split directly (no fp32 staging)
//   GEMMs: bf16 error-compensated split on mma.sync tensor cores,
//          cp.async double-buffered smem pipeline
//   C = Ahi@Bhi + Ahi@Blo + Alo@Bhi  (fp32 accumulate) ~ fp32 GEMM, ~6e-6
// ---------------------------------------------------------------------------

#define N_NODES 50000
#define M_PAD   50048      // 128 * 391
#define D_MAX   256
#define E_MAX   (1 << 20)

// Static scratch. Padding rows of AHI/ALO/BHI/BLO may hold stale data; they
// only influence GEMM output rows >= N_NODES, which are never stored.
__device__ float g_f1[(size_t)M_PAD * D_MAX];          // h2 fp32 (gather input)
__device__ __nv_bfloat16 g_ahi[(size_t)M_PAD * D_MAX];
__device__ __nv_bfloat16 g_alo[(size_t)M_PAD * D_MAX];
__device__ __nv_bfloat16 g_bhi[(size_t)M_PAD * D_MAX];
__device__ __nv_bfloat16 g_blo[(size_t)M_PAD * D_MAX];
__device__ __nv_bfloat16 g_wthi[4][256 * 256];         // transposed weights [N][K]
__device__ __nv_bfloat16 g_wtlo[4][256 * 256];
__device__ int g_deg[N_NODES];
__device__ int g_off[N_NODES + 1];
__device__ int g_pos[N_NODES];
__device__ int g_csr[E_MAX];
__device__ int g_idx_is64;

// ---------------------------------------------------------------------------
// PTX helpers (portable: ldmatrix + mma.sync + cp.async, sm_80+)
// ---------------------------------------------------------------------------
static __device__ __forceinline__ uint32_t smem_u32(const void* p) {
    uint32_t a;
    asm("{ .reg .u64 t; cvta.to.shared.u64 t, %1; cvt.u32.u64 %0, t; }" : "=r"(a) : "l"(p));
    return a;
}

static __device__ __forceinline__ void ldsm_x4(uint32_t* r, uint32_t addr) {
    asm volatile("ldmatrix.sync.aligned.m8n8.x4.shared.b16 {%0,%1,%2,%3}, [%4];"
                 : "=r"(r[0]), "=r"(r[1]), "=r"(r[2]), "=r"(r[3]) : "r"(addr));
}

static __device__ __forceinline__ void mma16816(float* c, const uint32_t* a, const uint32_t* b) {
    asm volatile("mma.sync.aligned.m16n8k16.row.col.f32.bf16.bf16.f32 "
                 "{%0,%1,%2,%3}, {%4,%5,%6,%7}, {%8,%9}, {%0,%1,%2,%3};"
                 : "+f"(c[0]), "+f"(c[1]), "+f"(c[2]), "+f"(c[3])
                 : "r"(a[0]), "r"(a[1]), "r"(a[2]), "r"(a[3]), "r"(b[0]), "r"(b[1]));
}

static __device__ __forceinline__ void cp16(uint32_t saddr, const void* gaddr) {
    asm volatile("cp.async.ca.shared.global [%0], [%1], 16;"
                 :: "r"(saddr), "l"(gaddr) : "memory");
}
#define CP_COMMIT()  asm volatile("cp.async.commit_group;" ::: "memory")
#define CP_WAIT(N)   asm volatile("cp.async.wait_group %0;" :: "n"(N) : "memory")

// Fetch edge endpoint pair (src, dst) for edge e, handling int64/int32 data.
static __device__ __forceinline__ void edge_pair(const void* ei, int e, int E, int& s, int& d) {
    if (g_idx_is64) {
        const long long* p = (const long long*)ei;
        s = (int)p[e];
        d = (int)p[e + E];
    } else {
        const int* p = (const int*)ei;
        s = p[e];
        d = p[e + E];
    }
    s = min(max(s, 0), N_NODES - 1);
    d = min(max(d, 0), N_NODES - 1);
}

// ---------------------------------------------------------------------------
// Small utility kernels
// ---------------------------------------------------------------------------
__global__ void detect_idx_kernel(const long long* __restrict__ ei) {
    if (threadIdx.x == 0 && blockIdx.x == 0) {
        int is64 = 1;
        #pragma unroll 1
        for (int i = 0; i < 64; ++i) {
            long long v = ei[i];
            if (v < 0 || v >= (long long)N_NODES) { is64 = 0; break; }
        }
        g_idx_is64 = is64;
    }
}

// One kernel prepping all 4 weights: W[K,N] fp32 -> Wt_hi/Wt_lo [N,K] bf16.
__global__ void prep_weights_all(const float* __restrict__ W1a, const float* __restrict__ W2a,
                                 const float* __restrict__ W1b, const float* __restrict__ W2b,
                                 __nv_bfloat16* __restrict__ hi, __nv_bfloat16* __restrict__ lo) {
    int i = blockIdx.x * blockDim.x + threadIdx.x;   // 0 .. 196608
    const float* W; int K, N, base, li;
    if (i < 32768)        { W = W1a; K = 128; N = 256; base = 0;          li = i; }
    else if (i < 98304)   { W = W2a; K = 256; N = 256; base = 1 * 65536;  li = i - 32768; }
    else if (i < 163840)  { W = W1b; K = 256; N = 256; base = 2 * 65536;  li = i - 98304; }
    else if (i < 196608)  { W = W2b; K = 256; N = 128; base = 3 * 65536;  li = i - 163840; }
    else return;
    int n = li / K, k = li % K;
    float v = W[(size_t)k * N + n];
    __nv_bfloat16 h = __float2bfloat16(v);
    hi[base + li] = h;
    lo[base + li] = __float2bfloat16(v - __bfloat162float(h));
}

// ---------------------------------------------------------------------------
// CSR build: zero -> histogram -> scan -> fill (re-run every launch).
// ---------------------------------------------------------------------------
__global__ void zero_deg_kernel(int n) {
    int i = blockIdx.x * blockDim.x + threadIdx.x;
    if (i < n) g_deg[i] = 0;
}

__global__ void hist_kernel(const void* __restrict__ ei, int E) {
    int e = blockIdx.x * blockDim.x + threadIdx.x;
    if (e >= E) return;
    int s, d;
    edge_pair(ei, e, E, s, d);
    atomicAdd(&g_deg[d], 1);
}

// One-block exclusive scan over g_deg. Writes g_off and g_pos.
__global__ __launch_bounds__(1024)
void scan_kernel(int n) {
    __shared__ int sums[1024];
    const int t = threadIdx.x;
    const int CH = (n + 1023) / 1024;
    const int base = t * CH;
    int s = 0;
    for (int j = 0; j < CH; ++j) {
        int idx = base + j;
        if (idx < n) s += g_deg[idx];
    }
    sums[t] = s;
    __syncthreads();
    for (int ofs = 1; ofs < 1024; ofs <<= 1) {
        int v = (t >= ofs) ? sums[t - ofs] : 0;
        __syncthreads();
        sums[t] += v;
        __syncthreads();
    }
    int run = (t > 0) ? sums[t - 1] : 0;
    for (int j = 0; j < CH; ++j) {
        int idx = base + j;
        if (idx < n) {
            g_off[idx] = run;
            g_pos[idx] = run;
            run += g_deg[idx];
        }
    }
    if (t == 1023) g_off[n] = sums[1023];
}

__global__ void fill_kernel(const void* __restrict__ ei, int E) {
    int e = blockIdx.x * blockDim.x + threadIdx.x;
    if (e >= E) return;
    int s, d;
    edge_pair(ei, e, E, s, d);
    int slot = atomicAdd(&g_pos[d], 1);
    g_csr[slot] = s;
}

// ---------------------------------------------------------------------------
// Gather + split: acc[i] = feat[i] + sum_{j in N(i)} feat[j]  (fp32),
// then emit bf16 hi/lo pair directly. One warp per node.
// VEC = float4 chunks per lane (1 -> D=128, 2 -> D=256).
// ---------------------------------------------------------------------------
template<int VEC>
__global__ void gather_split_kernel(const float* __restrict__ feat,
                                    __nv_bfloat16* __restrict__ hi,
                                    __nv_bfloat16* __restrict__ lo, int n) {
    const int D = VEC * 128;
    int w = (blockIdx.x * blockDim.x + threadIdx.x) >> 5;
    const int lane = threadIdx.x & 31;
    if (w >= n) return;

    const int beg = g_off[w];
    const int end = g_off[w + 1];

    float4 acc[VEC];
    #pragma unroll
    for (int v = 0; v < VEC; ++v)
        acc[v] = *reinterpret_cast<const float4*>(feat + (size_t)w * D + v * 128 + lane * 4);

    int i = beg;
    for (; i + 1 < end; i += 2) {
        int s0 = g_csr[i];
        int s1 = g_csr[i + 1];
        #pragma unroll
        for (int v = 0; v < VEC; ++v) {
            float4 a = *reinterpret_cast<const float4*>(feat + (size_t)s0 * D + v * 128 + lane * 4);
            float4 b = *reinterpret_cast<const float4*>(feat + (size_t)s1 * D + v * 128 + lane * 4);
            acc[v].x += a.x + b.x;
            acc[v].y += a.y + b.y;
            acc[v].z += a.z + b.z;
            acc[v].w += a.w + b.w;
        }
    }
    if (i < end) {
        int s0 = g_csr[i];
        #pragma unroll
        for (int v = 0; v < VEC; ++v) {
            float4 a = *reinterpret_cast<const float4*>(feat + (size_t)s0 * D + v * 128 + lane * 4);
            acc[v].x += a.x;
            acc[v].y += a.y;
            acc[v].z += a.z;
            acc[v].w += a.w;
        }
    }

    #pragma unroll
    for (int v = 0; v < VEC; ++v) {
        float vv[4] = { acc[v].x, acc[v].y, acc[v].z, acc[v].w };
        __nv_bfloat16 h[4], l[4];
        #pragma unroll
        for (int j = 0; j < 4; ++j) {
            h[j] = __float2bfloat16(vv[j]);
            l[j] = __float2bfloat16(vv[j] - __bfloat162float(h[j]));
        }
        *reinterpret_cast<uint2*>(hi + (size_t)w * D + v * 128 + lane * 4) =
            *reinterpret_cast<uint2*>(h);
        *reinterpret_cast<uint2*>(lo + (size_t)w * D + v * 128 + lane * 4) =
            *reinterpret_cast<uint2*>(l);
    }
}

// ---------------------------------------------------------------------------
// mma.sync GEMM: C[M,N] = A[M,K]@B^T (B transposed [N,K]).
// A,B as bf16 hi/lo splits; fp32 accumulate of 3 split products.
// CTA tile 128x128, BK=32, 256 threads (8 warps, 2x4), warp tile 64x32.
// cp.async double-buffered smem pipeline (no register staging).
// EPI: 0 = fp32 out (no relu), 1 = relu -> bf16 hi/lo split, 2 = relu -> fp32.
// ---------------------------------------------------------------------------
template<int EPI>
__global__ __launch_bounds__(256)
void mma_gemm(const __nv_bfloat16* __restrict__ Ahi, const __nv_bfloat16* __restrict__ Alo,
              const __nv_bfloat16* __restrict__ Bth, const __nv_bfloat16* __restrict__ Btl,
              const float* __restrict__ bias,
              float* __restrict__ outf,
              __nv_bfloat16* __restrict__ ohi, __nv_bfloat16* __restrict__ olo,
              int M, int K, int N) {
    constexpr int BM = 128, BK = 32, LDS = BK + 8;   // pad -> conflict-free ldmatrix
    __shared__ __nv_bfloat16 Ah[2][BM][LDS];
    __shared__ __nv_bfloat16 Al[2][BM][LDS];
    __shared__ __nv_bfloat16 Bh[2][BM][LDS];
    __shared__ __nv_bfloat16 Bl[2][BM][LDS];

    const int tid  = threadIdx.x;
    const int wid  = tid >> 5;
    const int lane = tid & 31;
    const int bm = blockIdx.y * 128;
    const int bn = blockIdx.x * 128;

    const int wm = (wid >> 2) * 64;   // warp m offset: 0 or 64
    const int wn = (wid & 3) * 32;    // warp n offset: 0,32,64,96

    const int lane_r = lane & 15;          // ldmatrix row within 16-row group
    const int lane_c = (lane >> 4) * 8;    // k-half

    float acc[4][4][4];
    #pragma unroll
    for (int mf = 0; mf < 4; ++mf)
        #pragma unroll
        for (int nf = 0; nf < 4; ++nf)
            #pragma unroll
            for (int c = 0; c < 4; ++c)
                acc[mf][nf][c] = 0.0f;

    // Global load mapping: row = tid>>2 (0..63) + it*64, col = (tid&3)*8.
    const int g_row0 = tid >> 2;
    const int g_col  = (tid & 3) * 8;

    // Per-thread smem cp.async destinations (byte addresses).
    uint32_t s_ah[2][2], s_al[2][2], s_bh[2][2], s_bl[2][2];
    #pragma unroll
    for (int b = 0; b < 2; ++b)
        #pragma unroll
        for (int it = 0; it < 2; ++it) {
            const int row = g_row0 + it * 64;
            s_ah[b][it] = smem_u32(&Ah[b][row][g_col]);
            s_al[b][it] = smem_u32(&Al[b][row][g_col]);
            s_bh[b][it] = smem_u32(&Bh[b][row][g_col]);
            s_bl[b][it] = smem_u32(&Bl[b][row][g_col]);
        }

    const int ktiles = K >> 5;

    // Issue async loads for k-tile kt into buffer b.
    auto load_tile = [&](int kt, int b) {
        const int k0 = kt << 5;
        #pragma unroll
        for (int it = 0; it < 2; ++it) {
            const int row = g_row0 + it * 64;
            const size_t ga = (size_t)(bm + row) * K + k0 + g_col;
            const size_t gb = (size_t)(bn + row) * K + k0 + g_col;
            cp16(s_ah[b][it], Ahi + ga);
            cp16(s_al[b][it], Alo + ga);
            cp16(s_bh[b][it], Bth + gb);
            cp16(s_bl[b][it], Btl + gb);
        }
        CP_COMMIT();
    };

    // Prologue: tile 0 in flight.
    load_tile(0, 0);

    #pragma unroll 1
    for (int kt = 0; kt < ktiles; ++kt) {
        const int buf = kt & 1;

        // Issue next tile into the other buffer (safe: previous compute on it
        // finished before this iteration's entry sync of last round).
        if (kt + 1 < ktiles) {
            load_tile(kt + 1, buf ^ 1);
            CP_WAIT(1);      // tile kt complete; tile kt+1 may be in flight
        } else {
            CP_WAIT(0);
        }
        __syncthreads();

        const uint32_t ah_base = smem_u32(&Ah[buf][0][0]);
        const uint32_t al_base = smem_u32(&Al[buf][0][0]);
        const uint32_t bh_base = smem_u32(&Bh[buf][0][0]);
        const uint32_t bl_base = smem_u32(&Bl[buf][0][0]);

        #pragma unroll
        for (int ks = 0; ks < 2; ++ks) {
            const uint32_t a_off = (uint32_t)(ks * 16 + lane_c) * 2;

            uint32_t ah[4][4], al[4][4];
            #pragma unroll
            for (int mf = 0; mf < 4; ++mf) {
                const uint32_t ro = (uint32_t)((wm + mf * 16 + lane_r) * LDS) * 2;
                ldsm_x4(ah[mf], ah_base + ro + a_off);
                ldsm_x4(al[mf], al_base + ro + a_off);
            }
            uint32_t bh[4][2], bl[4][2];
            #pragma unroll
            for (int np = 0; np < 2; ++np) {
                const uint32_t ro = (uint32_t)((wn + np * 16 + lane_r) * LDS) * 2;
                uint32_t r[4];
                ldsm_x4(r, bh_base + ro + a_off);
                bh[np * 2 + 0][0] = r[0]; bh[np * 2 + 0][1] = r[2];
                bh[np * 2 + 1][0] = r[1]; bh[np * 2 + 1][1] = r[3];
                ldsm_x4(r, bl_base + ro + a_off);
                bl[np * 2 + 0][0] = r[0]; bl[np * 2 + 0][1] = r[2];
                bl[np * 2 + 1][0] = r[1]; bl[np * 2 + 1][1] = r[3];
            }

            #pragma unroll
            for (int mf = 0; mf < 4; ++mf)
                #pragma unroll
                for (int nf = 0; nf < 4; ++nf) {
                    mma16816(acc[mf][nf], ah[mf], bh[nf]);
                    mma16816(acc[mf][nf], ah[mf], bl[nf]);
                    mma16816(acc[mf][nf], al[mf], bh[nf]);
                }
        }
        __syncthreads();
    }

    // Epilogue. Thread owns rows (gr, gr+8), cols 2*(lane%4)+{0,1} per fragment.
    const int gr = lane >> 2;
    const int gc = (lane & 3) * 2;
    #pragma unroll
    for (int mf = 0; mf < 4; ++mf) {
        const int row0 = bm + wm + mf * 16 + gr;
        const int row1 = row0 + 8;
        #pragma unroll
        for (int nf = 0; nf < 4; ++nf) {
            const int col = bn + wn + nf * 8 + gc;
            const float bz0 = bias[col], bz1 = bias[col + 1];
            float v00 = acc[mf][nf][0] + bz0, v01 = acc[mf][nf][1] + bz1;
            float v10 = acc[mf][nf][2] + bz0, v11 = acc[mf][nf][3] + bz1;
            if (EPI != 0) {
                v00 = fmaxf(v00, 0.f); v01 = fmaxf(v01, 0.f);
                v10 = fmaxf(v10, 0.f); v11 = fmaxf(v11, 0.f);
            }
            if (EPI == 1) {
                if (row0 < M) {
                    __nv_bfloat16 h0 = __float2bfloat16(v00), h1 = __float2bfloat16(v01);
                    __nv_bfloat162 hh; hh.x = h0; hh.y = h1;
                    __nv_bfloat162 ll;
                    ll.x = __float2bfloat16(v00 - __bfloat162float(h0));
                    ll.y = __float2bfloat16(v01 - __bfloat162float(h1));
                    *reinterpret_cast<__nv_bfloat162*>(ohi + (size_t)row0 * N + col) = hh;
                    *reinterpret_cast<__nv_bfloat162*>(olo + (size_t)row0 * N + col) = ll;
                }
                if (row1 < M) {
                    __nv_bfloat16 h0 = __float2bfloat16(v10), h1 = __float2bfloat16(v11);
                    __nv_bfloat162 hh; hh.x = h0; hh.y = h1;
                    __nv_bfloat162 ll;
                    ll.x = __float2bfloat16(v10 - __bfloat162float(h0));
                    ll.y = __float2bfloat16(v11 - __bfloat162float(h1));
                    *reinterpret_cast<__nv_bfloat162*>(ohi + (size_t)row1 * N + col) = hh;
                    *reinterpret_cast<__nv_bfloat162*>(olo + (size_t)row1 * N + col) = ll;
                }
            } else {
                if (row0 < M) {
                    float2 v; v.x = v00; v.y = v01;
                    *reinterpret_cast<float2*>(outf + (size_t)row0 * N + col) = v;
                }
                if (row1 < M) {
                    float2 v; v.x = v10; v.y = v11;
                    *reinterpret_cast<float2*>(outf + (size_t)row1 * N + col) = v;
                }
            }
        }
    }
}

// ---------------------------------------------------------------------------
// Launch
// ---------------------------------------------------------------------------
extern "C" void kernel_launch(void* const* d_in, const int* in_sizes, int n_in,
                              void* d_out, int out_size) {
    const float* x    = (const float*)d_in[0];
    const float* W1a  = (const float*)d_in[1];
    const float* b1a  = (const float*)d_in[2];
    const float* W2a  = (const float*)d_in[3];
    const float* b2a  = (const float*)d_in[4];
    const float* W1b  = (const float*)d_in[5];
    const float* b1b  = (const float*)d_in[6];
    const float* W2b  = (const float*)d_in[7];
    const float* b2b  = (const float*)d_in[8];
    const void*  ei   = d_in[9];

    const int M = N_NODES;
    const int E = in_sizes[9] / 2;

    float *F1;
    __nv_bfloat16 *AHI, *ALO, *BHI, *BLO, *WTH, *WTL;
    cudaGetSymbolAddress((void**)&F1, g_f1);
    cudaGetSymbolAddress((void**)&AHI, g_ahi);
    cudaGetSymbolAddress((void**)&ALO, g_alo);
    cudaGetSymbolAddress((void**)&BHI, g_bhi);
    cudaGetSymbolAddress((void**)&BLO, g_blo);
    cudaGetSymbolAddress((void**)&WTH, g_wthi);
    cudaGetSymbolAddress((void**)&WTL, g_wtlo);

    float* out = (float*)d_out;
    const int GY = M_PAD / 128;   // 391

    // Index dtype + weight prep + CSR build (shared by both layers).
    detect_idx_kernel<<<1, 1>>>((const long long*)ei);
    prep_weights_all<<<(196608 + 255) / 256, 256>>>(W1a, W2a, W1b, W2b, WTH, WTL);
    zero_deg_kernel<<<(N_NODES + 255) / 256, 256>>>(N_NODES);
    hist_kernel<<<(E + 255) / 256, 256>>>(ei, E);
    scan_kernel<<<1, 1024>>>(N_NODES);
    fill_kernel<<<(E + 255) / 256, 256>>>(ei, E);

    // ---- Layer 0 ----
    // AHI/ALO = split(x + gather(x))   (self term fused; no staging buffer)
    gather_split_kernel<1><<<(M * 32 + 255) / 256, 256>>>(x, AHI, ALO, M);
    // h1 = relu(agg0 @ W1a + b1a) -> split    [50000,128]@[128,256]
    mma_gemm<1><<<dim3(2, GY), 256>>>(AHI, ALO, WTH + 0 * 65536, WTL + 0 * 65536,
                                      b1a, nullptr, BHI, BLO, M, 128, 256);
    // h2 = relu(h1 @ W2a + b2a) -> fp32 F1    [50000,256]@[256,256]
    mma_gemm<2><<<dim3(2, GY), 256>>>(BHI, BLO, WTH + 1 * 65536, WTL + 1 * 65536,
                                      b2a, F1, nullptr, nullptr, M, 256, 256);

    // ---- Layer 1 ----
    // AHI/ALO = split(h2 + gather(h2))
    gather_split_kernel<2><<<(M * 32 + 255) / 256, 256>>>(F1, AHI, ALO, M);
    // h3 = relu(agg1 @ W1b + b1b) -> split    [50000,256]@[256,256]
    mma_gemm<1><<<dim3(2, GY), 256>>>(AHI, ALO, WTH + 2 * 65536, WTL + 2 * 65536,
                                      b1b, nullptr, BHI, BLO, M, 256, 256);
    // out = h3 @ W2b + b2b                    [50000,256]@[256,128]
    mma_gemm<0><<<dim3(1, GY), 256>>>(BHI, BLO, WTH + 3 * 65536, WTL + 3 * 65536,
                                      b2b, out, nullptr, nullptr, M, 256, 128);
}

// round 11
// speedup vs baseline: 1.7262x; 1.1955x over previous
#include <cuda_runtime.h>
#include <cuda_bf16.h>
#include <cstdint>

// ---------------------------------------------------------------------------
// GIN on GB300 (compute_103-portable):
//   aggregation: CSR build (coalesced 3-phase scan) + warp-per-node gather,
//                gather emits bf16 hi/lo split directly
//   GEMMs: bf16 error-compensated split on mma.sync tensor cores,
//          cp.async double-buffered, K/N compile-time specialized
//   C = Ahi@Bhi + Ahi@Blo + Alo@Bhi  (fp32 accumulate) ~ fp32 GEMM, ~6e-6
// ---------------------------------------------------------------------------

#define N_NODES 50000
#define M_PAD   50048      // 128 * 391
#define D_MAX   256
#define E_MAX   (1 << 20)
#define NB_SCAN 196        // ceil(N_NODES / 256)

// Static scratch. Padding rows of AHI/ALO/BHI/BLO may hold stale data; they
// only influence GEMM output rows >= N_NODES, which are never stored.
__device__ float g_f1[(size_t)M_PAD * D_MAX];          // h2 fp32 (gather input)
__device__ __nv_bfloat16 g_ahi[(size_t)M_PAD * D_MAX];
__device__ __nv_bfloat16 g_alo[(size_t)M_PAD * D_MAX];
__device__ __nv_bfloat16 g_bhi[(size_t)M_PAD * D_MAX];
__device__ __nv_bfloat16 g_blo[(size_t)M_PAD * D_MAX];
__device__ __nv_bfloat16 g_wthi[4][256 * 256];         // transposed weights [N][K]
__device__ __nv_bfloat16 g_wtlo[4][256 * 256];
__device__ int g_deg[N_NODES];
__device__ int g_off[N_NODES + 1];
__device__ int g_pos[N_NODES];
__device__ int g_csr[E_MAX];
__device__ int g_bsum[256];
__device__ int g_boff[256];
__device__ int g_idx_is64;

// ---------------------------------------------------------------------------
// PTX helpers (portable: ldmatrix + mma.sync + cp.async, sm_80+)
// ---------------------------------------------------------------------------
static __device__ __forceinline__ uint32_t smem_u32(const void* p) {
    uint32_t a;
    asm("{ .reg .u64 t; cvta.to.shared.u64 t, %1; cvt.u32.u64 %0, t; }" : "=r"(a) : "l"(p));
    return a;
}

static __device__ __forceinline__ void ldsm_x4(uint32_t* r, uint32_t addr) {
    asm volatile("ldmatrix.sync.aligned.m8n8.x4.shared.b16 {%0,%1,%2,%3}, [%4];"
                 : "=r"(r[0]), "=r"(r[1]), "=r"(r[2]), "=r"(r[3]) : "r"(addr));
}

static __device__ __forceinline__ void mma16816(float* c, const uint32_t* a, const uint32_t* b) {
    asm volatile("mma.sync.aligned.m16n8k16.row.col.f32.bf16.bf16.f32 "
                 "{%0,%1,%2,%3}, {%4,%5,%6,%7}, {%8,%9}, {%0,%1,%2,%3};"
                 : "+f"(c[0]), "+f"(c[1]), "+f"(c[2]), "+f"(c[3])
                 : "r"(a[0]), "r"(a[1]), "r"(a[2]), "r"(a[3]), "r"(b[0]), "r"(b[1]));
}

static __device__ __forceinline__ void cp16(uint32_t saddr, const void* gaddr) {
    asm volatile("cp.async.ca.shared.global [%0], [%1], 16;"
                 :: "r"(saddr), "l"(gaddr) : "memory");
}
#define CP_COMMIT()  asm volatile("cp.async.commit_group;" ::: "memory")
#define CP_WAIT(N)   asm volatile("cp.async.wait_group %0;" :: "n"(N) : "memory")

// Fetch edge endpoint pair (src, dst) for edge e, handling int64/int32 data.
static __device__ __forceinline__ void edge_pair(const void* ei, int e, int E, int& s, int& d) {
    if (g_idx_is64) {
        const long long* p = (const long long*)ei;
        s = (int)p[e];
        d = (int)p[e + E];
    } else {
        const int* p = (const int*)ei;
        s = p[e];
        d = p[e + E];
    }
    s = min(max(s, 0), N_NODES - 1);
    d = min(max(d, 0), N_NODES - 1);
}

// ---------------------------------------------------------------------------
// init: detect index dtype (block 0, thread 0) + zero degree array.
// ---------------------------------------------------------------------------
__global__ void init_kernel(const long long* __restrict__ ei, int n) {
    int i = blockIdx.x * blockDim.x + threadIdx.x;
    if (i == 0) {
        int is64 = 1;
        #pragma unroll 1
        for (int j = 0; j < 64; ++j) {
            long long v = ei[j];
            if (v < 0 || v >= (long long)N_NODES) { is64 = 0; break; }
        }
        g_idx_is64 = is64;
    }
    if (i < n) g_deg[i] = 0;
}

// One kernel prepping all 4 weights: W[K,N] fp32 -> Wt_hi/Wt_lo [N,K] bf16.
__global__ void prep_weights_all(const float* __restrict__ W1a, const float* __restrict__ W2a,
                                 const float* __restrict__ W1b, const float* __restrict__ W2b,
                                 __nv_bfloat16* __restrict__ hi, __nv_bfloat16* __restrict__ lo) {
    int i = blockIdx.x * blockDim.x + threadIdx.x;   // 0 .. 196608
    const float* W; int K, N, base, li;
    if (i < 32768)        { W = W1a; K = 128; N = 256; base = 0;          li = i; }
    else if (i < 98304)   { W = W2a; K = 256; N = 256; base = 1 * 65536;  li = i - 32768; }
    else if (i < 163840)  { W = W1b; K = 256; N = 256; base = 2 * 65536;  li = i - 98304; }
    else if (i < 196608)  { W = W2b; K = 256; N = 128; base = 3 * 65536;  li = i - 163840; }
    else return;
    int n = li / K, k = li % K;
    float v = W[(size_t)k * N + n];
    __nv_bfloat16 h = __float2bfloat16(v);
    hi[base + li] = h;
    lo[base + li] = __float2bfloat16(v - __bfloat162float(h));
}

// ---------------------------------------------------------------------------
// CSR build: hist -> 3-phase coalesced scan -> fill.
// ---------------------------------------------------------------------------
__global__ void hist_kernel(const void* __restrict__ ei, int E) {
    int e = blockIdx.x * blockDim.x + threadIdx.x;
    if (e >= E) return;
    int s, d;
    edge_pair(ei, e, E, s, d);
    atomicAdd(&g_deg[d], 1);
}

// Phase 1: per-block sum of 256 degrees (coalesced).
__global__ __launch_bounds__(256)
void scan_bsum_kernel(int n) {
    __shared__ int red[256];
    int i = blockIdx.x * 256 + threadIdx.x;
    red[threadIdx.x] = (i < n) ? g_deg[i] : 0;
    __syncthreads();
    #pragma unroll
    for (int ofs = 128; ofs > 0; ofs >>= 1) {
        if (threadIdx.x < ofs) red[threadIdx.x] += red[threadIdx.x + ofs];
        __syncthreads();
    }
    if (threadIdx.x == 0) g_bsum[blockIdx.x] = red[0];
}

// Phase 2: single block scans the (<=256) block sums -> exclusive offsets.
__global__ __launch_bounds__(256)
void scan_boff_kernel(int nb, int n) {
    __shared__ int s[256];
    int t = threadIdx.x;
    int v = (t < nb) ? g_bsum[t] : 0;
    s[t] = v;
    __syncthreads();
    #pragma unroll
    for (int ofs = 1; ofs < 256; ofs <<= 1) {
        int u = (t >= ofs) ? s[t - ofs] : 0;
        __syncthreads();
        s[t] += u;
        __syncthreads();
    }
    g_boff[t] = s[t] - v;                 // exclusive
    if (t == 255) g_off[n] = s[255];      // total edge count
}

// Phase 3: per-block exclusive scan + global offset -> g_off / g_pos.
__global__ __launch_bounds__(256)
void scan_write_kernel(int n) {
    __shared__ int s[256];
    int t = threadIdx.x;
    int i = blockIdx.x * 256 + t;
    int v = (i < n) ? g_deg[i] : 0;
    s[t] = v;
    __syncthreads();
    #pragma unroll
    for (int ofs = 1; ofs < 256; ofs <<= 1) {
        int u = (t >= ofs) ? s[t - ofs] : 0;
        __syncthreads();
        s[t] += u;
        __syncthreads();
    }
    if (i < n) {
        int off = g_boff[blockIdx.x] + s[t] - v;
        g_off[i] = off;
        g_pos[i] = off;
    }
}

__global__ void fill_kernel(const void* __restrict__ ei, int E) {
    int e = blockIdx.x * blockDim.x + threadIdx.x;
    if (e >= E) return;
    int s, d;
    edge_pair(ei, e, E, s, d);
    int slot = atomicAdd(&g_pos[d], 1);
    g_csr[slot] = s;
}

// ---------------------------------------------------------------------------
// Gather + split: acc[i] = feat[i] + sum_{j in N(i)} feat[j]  (fp32),
// then emit bf16 hi/lo pair directly. One warp per node, unroll 4 (MLP).
// VEC = float4 chunks per lane (1 -> D=128, 2 -> D=256).
// ---------------------------------------------------------------------------
template<int VEC>
__global__ void gather_split_kernel(const float* __restrict__ feat,
                                    __nv_bfloat16* __restrict__ hi,
                                    __nv_bfloat16* __restrict__ lo, int n) {
    const int D = VEC * 128;
    int w = (blockIdx.x * blockDim.x + threadIdx.x) >> 5;
    const int lane = threadIdx.x & 31;
    if (w >= n) return;

    const int beg = g_off[w];
    const int end = g_off[w + 1];

    float4 acc[VEC];
    #pragma unroll
    for (int v = 0; v < VEC; ++v)
        acc[v] = *reinterpret_cast<const float4*>(feat + (size_t)w * D + v * 128 + lane * 4);

    int i = beg;
    for (; i + 3 < end; i += 4) {
        int s0 = g_csr[i], s1 = g_csr[i + 1], s2 = g_csr[i + 2], s3 = g_csr[i + 3];
        #pragma unroll
        for (int v = 0; v < VEC; ++v) {
            float4 a = *reinterpret_cast<const float4*>(feat + (size_t)s0 * D + v * 128 + lane * 4);
            float4 b = *reinterpret_cast<const float4*>(feat + (size_t)s1 * D + v * 128 + lane * 4);
            float4 c = *reinterpret_cast<const float4*>(feat + (size_t)s2 * D + v * 128 + lane * 4);
            float4 d = *reinterpret_cast<const float4*>(feat + (size_t)s3 * D + v * 128 + lane * 4);
            acc[v].x += (a.x + b.x) + (c.x + d.x);
            acc[v].y += (a.y + b.y) + (c.y + d.y);
            acc[v].z += (a.z + b.z) + (c.z + d.z);
            acc[v].w += (a.w + b.w) + (c.w + d.w);
        }
    }
    for (; i < end; ++i) {
        int s0 = g_csr[i];
        #pragma unroll
        for (int v = 0; v < VEC; ++v) {
            float4 a = *reinterpret_cast<const float4*>(feat + (size_t)s0 * D + v * 128 + lane * 4);
            acc[v].x += a.x;
            acc[v].y += a.y;
            acc[v].z += a.z;
            acc[v].w += a.w;
        }
    }

    #pragma unroll
    for (int v = 0; v < VEC; ++v) {
        float vv[4] = { acc[v].x, acc[v].y, acc[v].z, acc[v].w };
        __nv_bfloat16 h[4], l[4];
        #pragma unroll
        for (int j = 0; j < 4; ++j) {
            h[j] = __float2bfloat16(vv[j]);
            l[j] = __float2bfloat16(vv[j] - __bfloat162float(h[j]));
        }
        *reinterpret_cast<uint2*>(hi + (size_t)w * D + v * 128 + lane * 4) =
            *reinterpret_cast<uint2*>(h);
        *reinterpret_cast<uint2*>(lo + (size_t)w * D + v * 128 + lane * 4) =
            *reinterpret_cast<uint2*>(l);
    }
}

// ---------------------------------------------------------------------------
// mma.sync GEMM: C[M,N] = A[M,K]@B^T (B transposed [N,K]).
// K, N compile-time; A,B as bf16 hi/lo splits; fp32 accumulate, 3 products.
// CTA tile 128x128, BK=32, 256 threads (8 warps, 2x4), warp tile 64x32.
// cp.async double-buffered smem pipeline.
// EPI: 0 = fp32 out (no relu), 1 = relu -> bf16 hi/lo split, 2 = relu -> fp32.
// ---------------------------------------------------------------------------
template<int EPI, int K, int N>
__global__ __launch_bounds__(256)
void mma_gemm(const __nv_bfloat16* __restrict__ Ahi, const __nv_bfloat16* __restrict__ Alo,
              const __nv_bfloat16* __restrict__ Bth, const __nv_bfloat16* __restrict__ Btl,
              const float* __restrict__ bias,
              float* __restrict__ outf,
              __nv_bfloat16* __restrict__ ohi, __nv_bfloat16* __restrict__ olo,
              int M) {
    constexpr int BM = 128, BK = 32, LDS = BK + 8;   // pad -> conflict-free ldmatrix
    constexpr int KTILES = K / BK;
    __shared__ __nv_bfloat16 Ah[2][BM][LDS];
    __shared__ __nv_bfloat16 Al[2][BM][LDS];
    __shared__ __nv_bfloat16 Bh[2][BM][LDS];
    __shared__ __nv_bfloat16 Bl[2][BM][LDS];

    const int tid  = threadIdx.x;
    const int wid  = tid >> 5;
    const int lane = tid & 31;
    const int bm = blockIdx.y * 128;
    const int bn = blockIdx.x * 128;

    const int wm = (wid >> 2) * 64;   // warp m offset: 0 or 64
    const int wn = (wid & 3) * 32;    // warp n offset: 0,32,64,96

    const int lane_r = lane & 15;          // ldmatrix row within 16-row group
    const int lane_c = (lane >> 4) * 8;    // k-half

    float acc[4][4][4];
    #pragma unroll
    for (int mf = 0; mf < 4; ++mf)
        #pragma unroll
        for (int nf = 0; nf < 4; ++nf)
            #pragma unroll
            for (int c = 0; c < 4; ++c)
                acc[mf][nf][c] = 0.0f;

    // Global load mapping: row = tid>>2 (0..63) + it*64, col = (tid&3)*8.
    const int g_row0 = tid >> 2;
    const int g_col  = (tid & 3) * 8;

    // Per-thread smem cp.async destinations (byte addresses).
    uint32_t s_ah[2][2], s_al[2][2], s_bh[2][2], s_bl[2][2];
    #pragma unroll
    for (int b = 0; b < 2; ++b)
        #pragma unroll
        for (int it = 0; it < 2; ++it) {
            const int row = g_row0 + it * 64;
            s_ah[b][it] = smem_u32(&Ah[b][row][g_col]);
            s_al[b][it] = smem_u32(&Al[b][row][g_col]);
            s_bh[b][it] = smem_u32(&Bh[b][row][g_col]);
            s_bl[b][it] = smem_u32(&Bl[b][row][g_col]);
        }

    // Issue async loads for k-tile kt into buffer b.
    auto load_tile = [&](int kt, int b) {
        const int k0 = kt << 5;
        #pragma unroll
        for (int it = 0; it < 2; ++it) {
            const int row = g_row0 + it * 64;
            const size_t ga = (size_t)(bm + row) * K + k0 + g_col;
            const size_t gb = (size_t)(bn + row) * K + k0 + g_col;
            cp16(s_ah[b][it], Ahi + ga);
            cp16(s_al[b][it], Alo + ga);
            cp16(s_bh[b][it], Bth + gb);
            cp16(s_bl[b][it], Btl + gb);
        }
        CP_COMMIT();
    };

    // Prologue: tile 0 in flight.
    load_tile(0, 0);

    #pragma unroll
    for (int kt = 0; kt < KTILES; ++kt) {
        const int buf = kt & 1;

        if (kt + 1 < KTILES) {
            load_tile(kt + 1, buf ^ 1);
            CP_WAIT(1);      // tile kt complete; tile kt+1 may be in flight
        } else {
            CP_WAIT(0);
        }
        __syncthreads();

        const uint32_t ah_base = smem_u32(&Ah[buf][0][0]);
        const uint32_t al_base = smem_u32(&Al[buf][0][0]);
        const uint32_t bh_base = smem_u32(&Bh[buf][0][0]);
        const uint32_t bl_base = smem_u32(&Bl[buf][0][0]);

        #pragma unroll
        for (int ks = 0; ks < 2; ++ks) {
            const uint32_t a_off = (uint32_t)(ks * 16 + lane_c) * 2;

            uint32_t ah[4][4], al[4][4];
            #pragma unroll
            for (int mf = 0; mf < 4; ++mf) {
                const uint32_t ro = (uint32_t)((wm + mf * 16 + lane_r) * LDS) * 2;
                ldsm_x4(ah[mf], ah_base + ro + a_off);
                ldsm_x4(al[mf], al_base + ro + a_off);
            }
            uint32_t bh[4][2], bl[4][2];
            #pragma unroll
            for (int np = 0; np < 2; ++np) {
                const uint32_t ro = (uint32_t)((wn + np * 16 + lane_r) * LDS) * 2;
                uint32_t r[4];
                ldsm_x4(r, bh_base + ro + a_off);
                bh[np * 2 + 0][0] = r[0]; bh[np * 2 + 0][1] = r[2];
                bh[np * 2 + 1][0] = r[1]; bh[np * 2 + 1][1] = r[3];
                ldsm_x4(r, bl_base + ro + a_off);
                bl[np * 2 + 0][0] = r[0]; bl[np * 2 + 0][1] = r[2];
                bl[np * 2 + 1][0] = r[1]; bl[np * 2 + 1][1] = r[3];
            }

            #pragma unroll
            for (int mf = 0; mf < 4; ++mf)
                #pragma unroll
                for (int nf = 0; nf < 4; ++nf) {
                    mma16816(acc[mf][nf], ah[mf], bh[nf]);
                    mma16816(acc[mf][nf], ah[mf], bl[nf]);
                    mma16816(acc[mf][nf], al[mf], bh[nf]);
                }
        }
        __syncthreads();
    }

    // Epilogue. Thread owns rows (gr, gr+8), cols 2*(lane%4)+{0,1} per fragment.
    const int gr = lane >> 2;
    const int gc = (lane & 3) * 2;
    #pragma unroll
    for (int mf = 0; mf < 4; ++mf) {
        const int row0 = bm + wm + mf * 16 + gr;
        const int row1 = row0 + 8;
        #pragma unroll
        for (int nf = 0; nf < 4; ++nf) {
            const int col = bn + wn + nf * 8 + gc;
            const float bz0 = bias[col], bz1 = bias[col + 1];
            float v00 = acc[mf][nf][0] + bz0, v01 = acc[mf][nf][1] + bz1;
            float v10 = acc[mf][nf][2] + bz0, v11 = acc[mf][nf][3] + bz1;
            if (EPI != 0) {
                v00 = fmaxf(v00, 0.f); v01 = fmaxf(v01, 0.f);
                v10 = fmaxf(v10, 0.f); v11 = fmaxf(v11, 0.f);
            }
            if (EPI == 1) {
                if (row0 < M) {
                    __nv_bfloat16 h0 = __float2bfloat16(v00), h1 = __float2bfloat16(v01);
                    __nv_bfloat162 hh; hh.x = h0; hh.y = h1;
                    __nv_bfloat162 ll;
                    ll.x = __float2bfloat16(v00 - __bfloat162float(h0));
                    ll.y = __float2bfloat16(v01 - __bfloat162float(h1));
                    *reinterpret_cast<__nv_bfloat162*>(ohi + (size_t)row0 * N + col) = hh;
                    *reinterpret_cast<__nv_bfloat162*>(olo + (size_t)row0 * N + col) = ll;
                }
                if (row1 < M) {
                    __nv_bfloat16 h0 = __float2bfloat16(v10), h1 = __float2bfloat16(v11);
                    __nv_bfloat162 hh; hh.x = h0; hh.y = h1;
                    __nv_bfloat162 ll;
                    ll.x = __float2bfloat16(v10 - __bfloat162float(h0));
                    ll.y = __float2bfloat16(v11 - __bfloat162float(h1));
                    *reinterpret_cast<__nv_bfloat162*>(ohi + (size_t)row1 * N + col) = hh;
                    *reinterpret_cast<__nv_bfloat162*>(olo + (size_t)row1 * N + col) = ll;
                }
            } else {
                if (row0 < M) {
                    float2 v; v.x = v00; v.y = v01;
                    *reinterpret_cast<float2*>(outf + (size_t)row0 * N + col) = v;
                }
                if (row1 < M) {
                    float2 v; v.x = v10; v.y = v11;
                    *reinterpret_cast<float2*>(outf + (size_t)row1 * N + col) = v;
                }
            }
        }
    }
}

// ---------------------------------------------------------------------------
// Launch
// ---------------------------------------------------------------------------
extern "C" void kernel_launch(void* const* d_in, const int* in_sizes, int n_in,
                              void* d_out, int out_size) {
    const float* x    = (const float*)d_in[0];
    const float* W1a  = (const float*)d_in[1];
    const float* b1a  = (const float*)d_in[2];
    const float* W2a  = (const float*)d_in[3];
    const float* b2a  = (const float*)d_in[4];
    const float* W1b  = (const float*)d_in[5];
    const float* b1b  = (const float*)d_in[6];
    const float* W2b  = (const float*)d_in[7];
    const float* b2b  = (const float*)d_in[8];
    const void*  ei   = d_in[9];

    const int M = N_NODES;
    const int E = in_sizes[9] / 2;

    float *F1;
    __nv_bfloat16 *AHI, *ALO, *BHI, *BLO, *WTH, *WTL;
    cudaGetSymbolAddress((void**)&F1, g_f1);
    cudaGetSymbolAddress((void**)&AHI, g_ahi);
    cudaGetSymbolAddress((void**)&ALO, g_alo);
    cudaGetSymbolAddress((void**)&BHI, g_bhi);
    cudaGetSymbolAddress((void**)&BLO, g_blo);
    cudaGetSymbolAddress((void**)&WTH, g_wthi);
    cudaGetSymbolAddress((void**)&WTL, g_wtlo);

    float* out = (float*)d_out;
    const int GY = M_PAD / 128;   // 391

    // Index dtype + zero degrees + weight prep + CSR build.
    init_kernel<<<(N_NODES + 255) / 256, 256>>>((const long long*)ei, N_NODES);
    prep_weights_all<<<(196608 + 255) / 256, 256>>>(W1a, W2a, W1b, W2b, WTH, WTL);
    hist_kernel<<<(E + 255) / 256, 256>>>(ei, E);
    scan_bsum_kernel<<<NB_SCAN, 256>>>(N_NODES);
    scan_boff_kernel<<<1, 256>>>(NB_SCAN, N_NODES);
    scan_write_kernel<<<NB_SCAN, 256>>>(N_NODES);
    fill_kernel<<<(E + 255) / 256, 256>>>(ei, E);

    // ---- Layer 0 ----
    // AHI/ALO = split(x + gather(x))
    gather_split_kernel<1><<<(M * 32 + 255) / 256, 256>>>(x, AHI, ALO, M);
    // h1 = relu(agg0 @ W1a + b1a) -> split    [50000,128]@[128,256]
    mma_gemm<1, 128, 256><<<dim3(2, GY), 256>>>(AHI, ALO, WTH + 0 * 65536, WTL + 0 * 65536,
                                                b1a, nullptr, BHI, BLO, M);
    // h2 = relu(h1 @ W2a + b2a) -> fp32 F1    [50000,256]@[256,256]
    mma_gemm<2, 256, 256><<<dim3(2, GY), 256>>>(BHI, BLO, WTH + 1 * 65536, WTL + 1 * 65536,
                                                b2a, F1, nullptr, nullptr, M);

    // ---- Layer 1 ----
    // AHI/ALO = split(h2 + gather(h2))
    gather_split_kernel<2><<<(M * 32 + 255) / 256, 256>>>(F1, AHI, ALO, M);
    // h3 = relu(agg1 @ W1b + b1b) -> split    [50000,256]@[256,256]
    mma_gemm<1, 256, 256><<<dim3(2, GY), 256>>>(AHI, ALO, WTH + 2 * 65536, WTL + 2 * 65536,
                                                b1b, nullptr, BHI, BLO, M);
    // out = h3 @ W2b + b2b                    [50000,256]@[256,128]
    mma_gemm<0, 256, 128><<<dim3(1, GY), 256>>>(BHI, BLO, WTH + 3 * 65536, WTL + 3 * 65536,
                                                b2b, out, nullptr, nullptr, M);
}

// round 12
// speedup vs baseline: 2.3253x; 1.3471x over previous
#include <cuda_runtime.h>
#include <cuda_fp16.h>
#include <cstdint>

// ---------------------------------------------------------------------------
// GIN on GB300 (compute_103-portable):
//   aggregation: CSR build (coalesced 3-phase scan) + warp-per-node gather,
//                gather emits fp16 hi/lo split directly
//   GEMMs: fp16 2-product error-compensated split on mma.sync tensor cores,
//          cp.async double-buffered, K/N compile-time specialized
//   C = (Ahi + Alo) @ Bfp16  (fp32 accumulate)  ~ rel_err 1e-4 (gate 1e-3)
// ---------------------------------------------------------------------------

#define N_NODES 50000
#define M_PAD   50048      // 128 * 391
#define D_MAX   256
#define E_MAX   (1 << 20)
#define NB_SCAN 196        // ceil(N_NODES / 256)

// Static scratch. Padding rows of AHI/ALO/BHI/BLO may hold stale data; they
// only influence GEMM output rows >= N_NODES, which are never stored.
__device__ float g_f1[(size_t)M_PAD * D_MAX];          // h2 fp32 (gather input)
__device__ __half g_ahi[(size_t)M_PAD * D_MAX];
__device__ __half g_alo[(size_t)M_PAD * D_MAX];
__device__ __half g_bhi[(size_t)M_PAD * D_MAX];
__device__ __half g_blo[(size_t)M_PAD * D_MAX];
__device__ __half g_wt[4][256 * 256];                  // transposed weights [N][K]
__device__ int g_deg[N_NODES];
__device__ int g_off[N_NODES + 1];
__device__ int g_pos[N_NODES];
__device__ int g_csr[E_MAX];
__device__ int g_bsum[256];
__device__ int g_boff[256];
__device__ int g_idx_is64;

// ---------------------------------------------------------------------------
// PTX helpers (portable: ldmatrix + mma.sync + cp.async, sm_80+)
// ---------------------------------------------------------------------------
static __device__ __forceinline__ uint32_t smem_u32(const void* p) {
    uint32_t a;
    asm("{ .reg .u64 t; cvta.to.shared.u64 t, %1; cvt.u32.u64 %0, t; }" : "=r"(a) : "l"(p));
    return a;
}

static __device__ __forceinline__ void ldsm_x4(uint32_t* r, uint32_t addr) {
    asm volatile("ldmatrix.sync.aligned.m8n8.x4.shared.b16 {%0,%1,%2,%3}, [%4];"
                 : "=r"(r[0]), "=r"(r[1]), "=r"(r[2]), "=r"(r[3]) : "r"(addr));
}

static __device__ __forceinline__ void mma16816(float* c, const uint32_t* a, const uint32_t* b) {
    asm volatile("mma.sync.aligned.m16n8k16.row.col.f32.f16.f16.f32 "
                 "{%0,%1,%2,%3}, {%4,%5,%6,%7}, {%8,%9}, {%0,%1,%2,%3};"
                 : "+f"(c[0]), "+f"(c[1]), "+f"(c[2]), "+f"(c[3])
                 : "r"(a[0]), "r"(a[1]), "r"(a[2]), "r"(a[3]), "r"(b[0]), "r"(b[1]));
}

static __device__ __forceinline__ void cp16(uint32_t saddr, const void* gaddr) {
    asm volatile("cp.async.ca.shared.global [%0], [%1], 16;"
                 :: "r"(saddr), "l"(gaddr) : "memory");
}
#define CP_COMMIT()  asm volatile("cp.async.commit_group;" ::: "memory")
#define CP_WAIT(N)   asm volatile("cp.async.wait_group %0;" :: "n"(N) : "memory")

// Fetch edge endpoint pair (src, dst) for edge e, handling int64/int32 data.
static __device__ __forceinline__ void edge_pair(const void* ei, int e, int E, int& s, int& d) {
    if (g_idx_is64) {
        const long long* p = (const long long*)ei;
        s = (int)p[e];
        d = (int)p[e + E];
    } else {
        const int* p = (const int*)ei;
        s = p[e];
        d = p[e + E];
    }
    s = min(max(s, 0), N_NODES - 1);
    d = min(max(d, 0), N_NODES - 1);
}

// ---------------------------------------------------------------------------
// init: detect index dtype (block 0, thread 0) + zero degree array.
// ---------------------------------------------------------------------------
__global__ void init_kernel(const long long* __restrict__ ei, int n) {
    int i = blockIdx.x * blockDim.x + threadIdx.x;
    if (i == 0) {
        int is64 = 1;
        #pragma unroll 1
        for (int j = 0; j < 64; ++j) {
            long long v = ei[j];
            if (v < 0 || v >= (long long)N_NODES) { is64 = 0; break; }
        }
        g_idx_is64 = is64;
    }
    if (i < n) g_deg[i] = 0;
}

// One kernel prepping all 4 weights: W[K,N] fp32 -> Wt [N,K] fp16.
__global__ void prep_weights_all(const float* __restrict__ W1a, const float* __restrict__ W2a,
                                 const float* __restrict__ W1b, const float* __restrict__ W2b,
                                 __half* __restrict__ wt) {
    int i = blockIdx.x * blockDim.x + threadIdx.x;   // 0 .. 196608
    const float* W; int K, N, base, li;
    if (i < 32768)        { W = W1a; K = 128; N = 256; base = 0;          li = i; }
    else if (i < 98304)   { W = W2a; K = 256; N = 256; base = 1 * 65536;  li = i - 32768; }
    else if (i < 163840)  { W = W1b; K = 256; N = 256; base = 2 * 65536;  li = i - 98304; }
    else if (i < 196608)  { W = W2b; K = 256; N = 128; base = 3 * 65536;  li = i - 163840; }
    else return;
    int n = li / K, k = li % K;
    wt[base + li] = __float2half(W[(size_t)k * N + n]);
}

// ---------------------------------------------------------------------------
// CSR build: hist -> 3-phase coalesced scan -> fill.
// ---------------------------------------------------------------------------
__global__ void hist_kernel(const void* __restrict__ ei, int E) {
    int e = blockIdx.x * blockDim.x + threadIdx.x;
    if (e >= E) return;
    int s, d;
    edge_pair(ei, e, E, s, d);
    atomicAdd(&g_deg[d], 1);
}

__global__ __launch_bounds__(256)
void scan_bsum_kernel(int n) {
    __shared__ int red[256];
    int i = blockIdx.x * 256 + threadIdx.x;
    red[threadIdx.x] = (i < n) ? g_deg[i] : 0;
    __syncthreads();
    #pragma unroll
    for (int ofs = 128; ofs > 0; ofs >>= 1) {
        if (threadIdx.x < ofs) red[threadIdx.x] += red[threadIdx.x + ofs];
        __syncthreads();
    }
    if (threadIdx.x == 0) g_bsum[blockIdx.x] = red[0];
}

__global__ __launch_bounds__(256)
void scan_boff_kernel(int nb, int n) {
    __shared__ int s[256];
    int t = threadIdx.x;
    int v = (t < nb) ? g_bsum[t] : 0;
    s[t] = v;
    __syncthreads();
    #pragma unroll
    for (int ofs = 1; ofs < 256; ofs <<= 1) {
        int u = (t >= ofs) ? s[t - ofs] : 0;
        __syncthreads();
        s[t] += u;
        __syncthreads();
    }
    g_boff[t] = s[t] - v;                 // exclusive
    if (t == 255) g_off[n] = s[255];      // total edge count
}

__global__ __launch_bounds__(256)
void scan_write_kernel(int n) {
    __shared__ int s[256];
    int t = threadIdx.x;
    int i = blockIdx.x * 256 + t;
    int v = (i < n) ? g_deg[i] : 0;
    s[t] = v;
    __syncthreads();
    #pragma unroll
    for (int ofs = 1; ofs < 256; ofs <<= 1) {
        int u = (t >= ofs) ? s[t - ofs] : 0;
        __syncthreads();
        s[t] += u;
        __syncthreads();
    }
    if (i < n) {
        int off = g_boff[blockIdx.x] + s[t] - v;
        g_off[i] = off;
        g_pos[i] = off;
    }
}

__global__ void fill_kernel(const void* __restrict__ ei, int E) {
    int e = blockIdx.x * blockDim.x + threadIdx.x;
    if (e >= E) return;
    int s, d;
    edge_pair(ei, e, E, s, d);
    int slot = atomicAdd(&g_pos[d], 1);
    g_csr[slot] = s;
}

// ---------------------------------------------------------------------------
// Gather + split: acc[i] = feat[i] + sum_{j in N(i)} feat[j]  (fp32),
// then emit fp16 hi/lo pair directly. One warp per node, unroll 4 (MLP).
// VEC = float4 chunks per lane (1 -> D=128, 2 -> D=256).
// ---------------------------------------------------------------------------
template<int VEC>
__global__ void gather_split_kernel(const float* __restrict__ feat,
                                    __half* __restrict__ hi,
                                    __half* __restrict__ lo, int n) {
    const int D = VEC * 128;
    int w = (blockIdx.x * blockDim.x + threadIdx.x) >> 5;
    const int lane = threadIdx.x & 31;
    if (w >= n) return;

    const int beg = g_off[w];
    const int end = g_off[w + 1];

    float4 acc[VEC];
    #pragma unroll
    for (int v = 0; v < VEC; ++v)
        acc[v] = *reinterpret_cast<const float4*>(feat + (size_t)w * D + v * 128 + lane * 4);

    int i = beg;
    for (; i + 3 < end; i += 4) {
        int s0 = g_csr[i], s1 = g_csr[i + 1], s2 = g_csr[i + 2], s3 = g_csr[i + 3];
        #pragma unroll
        for (int v = 0; v < VEC; ++v) {
            float4 a = *reinterpret_cast<const float4*>(feat + (size_t)s0 * D + v * 128 + lane * 4);
            float4 b = *reinterpret_cast<const float4*>(feat + (size_t)s1 * D + v * 128 + lane * 4);
            float4 c = *reinterpret_cast<const float4*>(feat + (size_t)s2 * D + v * 128 + lane * 4);
            float4 d = *reinterpret_cast<const float4*>(feat + (size_t)s3 * D + v * 128 + lane * 4);
            acc[v].x += (a.x + b.x) + (c.x + d.x);
            acc[v].y += (a.y + b.y) + (c.y + d.y);
            acc[v].z += (a.z + b.z) + (c.z + d.z);
            acc[v].w += (a.w + b.w) + (c.w + d.w);
        }
    }
    for (; i < end; ++i) {
        int s0 = g_csr[i];
        #pragma unroll
        for (int v = 0; v < VEC; ++v) {
            float4 a = *reinterpret_cast<const float4*>(feat + (size_t)s0 * D + v * 128 + lane * 4);
            acc[v].x += a.x;
            acc[v].y += a.y;
            acc[v].z += a.z;
            acc[v].w += a.w;
        }
    }

    #pragma unroll
    for (int v = 0; v < VEC; ++v) {
        float vv[4] = { acc[v].x, acc[v].y, acc[v].z, acc[v].w };
        __half h[4], l[4];
        #pragma unroll
        for (int j = 0; j < 4; ++j) {
            h[j] = __float2half(vv[j]);
            l[j] = __float2half(vv[j] - __half2float(h[j]));
        }
        *reinterpret_cast<uint2*>(hi + (size_t)w * D + v * 128 + lane * 4) =
            *reinterpret_cast<uint2*>(h);
        *reinterpret_cast<uint2*>(lo + (size_t)w * D + v * 128 + lane * 4) =
            *reinterpret_cast<uint2*>(l);
    }
}

// ---------------------------------------------------------------------------
// mma.sync GEMM: C[M,N] = A[M,K]@B^T (B transposed [N,K], fp16).
// K, N compile-time; A as fp16 hi/lo split; fp32 accumulate, 2 products.
// CTA tile 128x128, BK=32, 256 threads (8 warps, 2x4), warp tile 64x32.
// cp.async double-buffered smem pipeline. 60KB smem -> 3 CTAs/SM.
// EPI: 0 = fp32 out (no relu), 1 = relu -> fp16 hi/lo split, 2 = relu -> fp32.
// ---------------------------------------------------------------------------
template<int EPI, int K, int N>
__global__ __launch_bounds__(256)
void mma_gemm(const __half* __restrict__ Ahi, const __half* __restrict__ Alo,
              const __half* __restrict__ Bt,
              const float* __restrict__ bias,
              float* __restrict__ outf,
              __half* __restrict__ ohi, __half* __restrict__ olo,
              int M) {
    constexpr int BM = 128, BK = 32, LDS = BK + 8;   // pad -> conflict-free ldmatrix
    constexpr int KTILES = K / BK;
    __shared__ __half Ah[2][BM][LDS];
    __shared__ __half Al[2][BM][LDS];
    __shared__ __half Bh[2][BM][LDS];

    const int tid  = threadIdx.x;
    const int wid  = tid >> 5;
    const int lane = tid & 31;
    const int bm = blockIdx.y * 128;
    const int bn = blockIdx.x * 128;

    const int wm = (wid >> 2) * 64;   // warp m offset: 0 or 64
    const int wn = (wid & 3) * 32;    // warp n offset: 0,32,64,96

    const int lane_r = lane & 15;          // ldmatrix row within 16-row group
    const int lane_c = (lane >> 4) * 8;    // k-half

    float acc[4][4][4];
    #pragma unroll
    for (int mf = 0; mf < 4; ++mf)
        #pragma unroll
        for (int nf = 0; nf < 4; ++nf)
            #pragma unroll
            for (int c = 0; c < 4; ++c)
                acc[mf][nf][c] = 0.0f;

    // Global load mapping: row = tid>>2 (0..63) + it*64, col = (tid&3)*8.
    const int g_row0 = tid >> 2;
    const int g_col  = (tid & 3) * 8;

    // Per-thread smem cp.async destinations (byte addresses).
    uint32_t s_ah[2][2], s_al[2][2], s_bh[2][2];
    #pragma unroll
    for (int b = 0; b < 2; ++b)
        #pragma unroll
        for (int it = 0; it < 2; ++it) {
            const int row = g_row0 + it * 64;
            s_ah[b][it] = smem_u32(&Ah[b][row][g_col]);
            s_al[b][it] = smem_u32(&Al[b][row][g_col]);
            s_bh[b][it] = smem_u32(&Bh[b][row][g_col]);
        }

    // Issue async loads for k-tile kt into buffer b.
    auto load_tile = [&](int kt, int b) {
        const int k0 = kt << 5;
        #pragma unroll
        for (int it = 0; it < 2; ++it) {
            const int row = g_row0 + it * 64;
            const size_t ga = (size_t)(bm + row) * K + k0 + g_col;
            const size_t gb = (size_t)(bn + row) * K + k0 + g_col;
            cp16(s_ah[b][it], Ahi + ga);
            cp16(s_al[b][it], Alo + ga);
            cp16(s_bh[b][it], Bt + gb);
        }
        CP_COMMIT();
    };

    // Prologue: tile 0 in flight.
    load_tile(0, 0);

    #pragma unroll
    for (int kt = 0; kt < KTILES; ++kt) {
        const int buf = kt & 1;

        if (kt + 1 < KTILES) {
            load_tile(kt + 1, buf ^ 1);
            CP_WAIT(1);      // tile kt complete; tile kt+1 may be in flight
        } else {
            CP_WAIT(0);
        }
        __syncthreads();

        const uint32_t ah_base = smem_u32(&Ah[buf][0][0]);
        const uint32_t al_base = smem_u32(&Al[buf][0][0]);
        const uint32_t bh_base = smem_u32(&Bh[buf][0][0]);

        #pragma unroll
        for (int ks = 0; ks < 2; ++ks) {
            const uint32_t a_off = (uint32_t)(ks * 16 + lane_c) * 2;

            uint32_t ah[4][4], al[4][4];
            #pragma unroll
            for (int mf = 0; mf < 4; ++mf) {
                const uint32_t ro = (uint32_t)((wm + mf * 16 + lane_r) * LDS) * 2;
                ldsm_x4(ah[mf], ah_base + ro + a_off);
                ldsm_x4(al[mf], al_base + ro + a_off);
            }
            uint32_t bh[4][2];
            #pragma unroll
            for (int np = 0; np < 2; ++np) {
                const uint32_t ro = (uint32_t)((wn + np * 16 + lane_r) * LDS) * 2;
                uint32_t r[4];
                ldsm_x4(r, bh_base + ro + a_off);
                bh[np * 2 + 0][0] = r[0]; bh[np * 2 + 0][1] = r[2];
                bh[np * 2 + 1][0] = r[1]; bh[np * 2 + 1][1] = r[3];
            }

            #pragma unroll
            for (int mf = 0; mf < 4; ++mf)
                #pragma unroll
                for (int nf = 0; nf < 4; ++nf) {
                    mma16816(acc[mf][nf], ah[mf], bh[nf]);
                    mma16816(acc[mf][nf], al[mf], bh[nf]);
                }
        }
        __syncthreads();
    }

    // Epilogue. Thread owns rows (gr, gr+8), cols 2*(lane%4)+{0,1} per fragment.
    const int gr = lane >> 2;
    const int gc = (lane & 3) * 2;
    #pragma unroll
    for (int mf = 0; mf < 4; ++mf) {
        const int row0 = bm + wm + mf * 16 + gr;
        const int row1 = row0 + 8;
        #pragma unroll
        for (int nf = 0; nf < 4; ++nf) {
            const int col = bn + wn + nf * 8 + gc;
            const float bz0 = bias[col], bz1 = bias[col + 1];
            float v00 = acc[mf][nf][0] + bz0, v01 = acc[mf][nf][1] + bz1;
            float v10 = acc[mf][nf][2] + bz0, v11 = acc[mf][nf][3] + bz1;
            if (EPI != 0) {
                v00 = fmaxf(v00, 0.f); v01 = fmaxf(v01, 0.f);
                v10 = fmaxf(v10, 0.f); v11 = fmaxf(v11, 0.f);
            }
            if (EPI == 1) {
                if (row0 < M) {
                    __half h0 = __float2half(v00), h1 = __float2half(v01);
                    __half2 hh; hh.x = h0; hh.y = h1;
                    __half2 ll;
                    ll.x = __float2half(v00 - __half2float(h0));
                    ll.y = __float2half(v01 - __half2float(h1));
                    *reinterpret_cast<__half2*>(ohi + (size_t)row0 * N + col) = hh;
                    *reinterpret_cast<__half2*>(olo + (size_t)row0 * N + col) = ll;
                }
                if (row1 < M) {
                    __half h0 = __float2half(v10), h1 = __float2half(v11);
                    __half2 hh; hh.x = h0; hh.y = h1;
                    __half2 ll;
                    ll.x = __float2half(v10 - __half2float(h0));
                    ll.y = __float2half(v11 - __half2float(h1));
                    *reinterpret_cast<__half2*>(ohi + (size_t)row1 * N + col) = hh;
                    *reinterpret_cast<__half2*>(olo + (size_t)row1 * N + col) = ll;
                }
            } else {
                if (row0 < M) {
                    float2 v; v.x = v00; v.y = v01;
                    *reinterpret_cast<float2*>(outf + (size_t)row0 * N + col) = v;
                }
                if (row1 < M) {
                    float2 v; v.x = v10; v.y = v11;
                    *reinterpret_cast<float2*>(outf + (size_t)row1 * N + col) = v;
                }
            }
        }
    }
}

// ---------------------------------------------------------------------------
// Launch
// ---------------------------------------------------------------------------
extern "C" void kernel_launch(void* const* d_in, const int* in_sizes, int n_in,
                              void* d_out, int out_size) {
    const float* x    = (const float*)d_in[0];
    const float* W1a  = (const float*)d_in[1];
    const float* b1a  = (const float*)d_in[2];
    const float* W2a  = (const float*)d_in[3];
    const float* b2a  = (const float*)d_in[4];
    const float* W1b  = (const float*)d_in[5];
    const float* b1b  = (const float*)d_in[6];
    const float* W2b  = (const float*)d_in[7];
    const float* b2b  = (const float*)d_in[8];
    const void*  ei   = d_in[9];

    const int M = N_NODES;
    const int E = in_sizes[9] / 2;

    float *F1;
    __half *AHI, *ALO, *BHI, *BLO, *WT;
    cudaGetSymbolAddress((void**)&F1, g_f1);
    cudaGetSymbolAddress((void**)&AHI, g_ahi);
    cudaGetSymbolAddress((void**)&ALO, g_alo);
    cudaGetSymbolAddress((void**)&BHI, g_bhi);
    cudaGetSymbolAddress((void**)&BLO, g_blo);
    cudaGetSymbolAddress((void**)&WT, g_wt);

    float* out = (float*)d_out;
    const int GY = M_PAD / 128;   // 391

    // Index dtype + zero degrees + weight prep + CSR build.
    init_kernel<<<(N_NODES + 255) / 256, 256>>>((const long long*)ei, N_NODES);
    prep_weights_all<<<(196608 + 255) / 256, 256>>>(W1a, W2a, W1b, W2b, WT);
    hist_kernel<<<(E + 255) / 256, 256>>>(ei, E);
    scan_bsum_kernel<<<NB_SCAN, 256>>>(N_NODES);
    scan_boff_kernel<<<1, 256>>>(NB_SCAN, N_NODES);
    scan_write_kernel<<<NB_SCAN, 256>>>(N_NODES);
    fill_kernel<<<(E + 255) / 256, 256>>>(ei, E);

    // ---- Layer 0 ----
    // AHI/ALO = split(x + gather(x))
    gather_split_kernel<1><<<(M * 32 + 255) / 256, 256>>>(x, AHI, ALO, M);
    // h1 = relu(agg0 @ W1a + b1a) -> split    [50000,128]@[128,256]
    mma_gemm<1, 128, 256><<<dim3(2, GY), 256>>>(AHI, ALO, WT + 0 * 65536,
                                                b1a, nullptr, BHI, BLO, M);
    // h2 = relu(h1 @ W2a + b2a) -> fp32 F1    [50000,256]@[256,256]
    mma_gemm<2, 256, 256><<<dim3(2, GY), 256>>>(BHI, BLO, WT + 1 * 65536,
                                                b2a, F1, nullptr, nullptr, M);

    // ---- Layer 1 ----
    // AHI/ALO = split(h2 + gather(h2))
    gather_split_kernel<2><<<(M * 32 + 255) / 256, 256>>>(F1, AHI, ALO, M);
    // h3 = relu(agg1 @ W1b + b1b) -> split    [50000,256]@[256,256]
    mma_gemm<1, 256, 256><<<dim3(2, GY), 256>>>(AHI, ALO, WT + 2 * 65536,
                                                b1b, nullptr, BHI, BLO, M);
    // out = h3 @ W2b + b2b                    [50000,256]@[256,128]
    mma_gemm<0, 256, 128><<<dim3(1, GY), 256>>>(BHI, BLO, WT + 3 * 65536,
                                                b2b, out, nullptr, nullptr, M);
}

// round 13
// speedup vs baseline: 3.1483x; 1.3539x over previous
#include <cuda_runtime.h>
#include <cuda_fp16.h>
#include <cstdint>

// ---------------------------------------------------------------------------
// GIN on GB300 (compute_103-portable):
//   aggregation: CSR build (coalesced 3-phase scan) + warp-per-node gather,
//                gather emits fp16 directly
//   GEMMs: pure fp16 mma.sync (fp32 accumulate), cp.async double-buffered,
//          K/N compile-time specialized
//   rel_err budget: W and A each rounded to fp16 -> ~3.7e-4 (gate 1e-3)
// ---------------------------------------------------------------------------

#define N_NODES 50000
#define M_PAD   50048      // 128 * 391
#define D_MAX   256
#define E_MAX   (1 << 20)
#define NB_SCAN 196        // ceil(N_NODES / 256)

// Static scratch. Padding rows of g_a/g_b may hold stale data; they only
// influence GEMM output rows >= N_NODES, which are never stored.
__device__ float g_f1[(size_t)M_PAD * D_MAX];          // h2 fp32 (gather input)
__device__ __half g_a[(size_t)M_PAD * D_MAX];          // GEMM A operand
__device__ __half g_b[(size_t)M_PAD * D_MAX];          // GEMM intermediate
__device__ __half g_wt[4][256 * 256];                  // transposed weights [N][K]
__device__ int g_deg[N_NODES];
__device__ int g_off[N_NODES + 1];
__device__ int g_pos[N_NODES];
__device__ int g_csr[E_MAX];
__device__ int g_bsum[256];
__device__ int g_boff[256];
__device__ int g_idx_is64;

// ---------------------------------------------------------------------------
// PTX helpers (portable: ldmatrix + mma.sync + cp.async, sm_80+)
// ---------------------------------------------------------------------------
static __device__ __forceinline__ uint32_t smem_u32(const void* p) {
    uint32_t a;
    asm("{ .reg .u64 t; cvta.to.shared.u64 t, %1; cvt.u32.u64 %0, t; }" : "=r"(a) : "l"(p));
    return a;
}

static __device__ __forceinline__ void ldsm_x4(uint32_t* r, uint32_t addr) {
    asm volatile("ldmatrix.sync.aligned.m8n8.x4.shared.b16 {%0,%1,%2,%3}, [%4];"
                 : "=r"(r[0]), "=r"(r[1]), "=r"(r[2]), "=r"(r[3]) : "r"(addr));
}

static __device__ __forceinline__ void mma16816(float* c, const uint32_t* a, const uint32_t* b) {
    asm volatile("mma.sync.aligned.m16n8k16.row.col.f32.f16.f16.f32 "
                 "{%0,%1,%2,%3}, {%4,%5,%6,%7}, {%8,%9}, {%0,%1,%2,%3};"
                 : "+f"(c[0]), "+f"(c[1]), "+f"(c[2]), "+f"(c[3])
                 : "r"(a[0]), "r"(a[1]), "r"(a[2]), "r"(a[3]), "r"(b[0]), "r"(b[1]));
}

static __device__ __forceinline__ void cp16(uint32_t saddr, const void* gaddr) {
    asm volatile("cp.async.ca.shared.global [%0], [%1], 16;"
                 :: "r"(saddr), "l"(gaddr) : "memory");
}
#define CP_COMMIT()  asm volatile("cp.async.commit_group;" ::: "memory")
#define CP_WAIT(N)   asm volatile("cp.async.wait_group %0;" :: "n"(N) : "memory")

// Fetch edge endpoint pair (src, dst) for edge e, handling int64/int32 data.
static __device__ __forceinline__ void edge_pair(const void* ei, int e, int E, int& s, int& d) {
    if (g_idx_is64) {
        const long long* p = (const long long*)ei;
        s = (int)p[e];
        d = (int)p[e + E];
    } else {
        const int* p = (const int*)ei;
        s = p[e];
        d = p[e + E];
    }
    s = min(max(s, 0), N_NODES - 1);
    d = min(max(d, 0), N_NODES - 1);
}

// ---------------------------------------------------------------------------
// init: detect index dtype (block 0, thread 0) + zero degree array.
// ---------------------------------------------------------------------------
__global__ void init_kernel(const long long* __restrict__ ei, int n) {
    int i = blockIdx.x * blockDim.x + threadIdx.x;
    if (i == 0) {
        int is64 = 1;
        #pragma unroll 1
        for (int j = 0; j < 64; ++j) {
            long long v = ei[j];
            if (v < 0 || v >= (long long)N_NODES) { is64 = 0; break; }
        }
        g_idx_is64 = is64;
    }
    if (i < n) g_deg[i] = 0;
}

// One kernel prepping all 4 weights: W[K,N] fp32 -> Wt [N,K] fp16.
__global__ void prep_weights_all(const float* __restrict__ W1a, const float* __restrict__ W2a,
                                 const float* __restrict__ W1b, const float* __restrict__ W2b,
                                 __half* __restrict__ wt) {
    int i = blockIdx.x * blockDim.x + threadIdx.x;   // 0 .. 196608
    const float* W; int K, N, base, li;
    if (i < 32768)        { W = W1a; K = 128; N = 256; base = 0;          li = i; }
    else if (i < 98304)   { W = W2a; K = 256; N = 256; base = 1 * 65536;  li = i - 32768; }
    else if (i < 163840)  { W = W1b; K = 256; N = 256; base = 2 * 65536;  li = i - 98304; }
    else if (i < 196608)  { W = W2b; K = 256; N = 128; base = 3 * 65536;  li = i - 163840; }
    else return;
    int n = li / K, k = li % K;
    wt[base + li] = __float2half(W[(size_t)k * N + n]);
}

// ---------------------------------------------------------------------------
// CSR build: hist -> 3-phase coalesced scan -> fill.
// ---------------------------------------------------------------------------
__global__ void hist_kernel(const void* __restrict__ ei, int E) {
    int e = blockIdx.x * blockDim.x + threadIdx.x;
    if (e >= E) return;
    int s, d;
    edge_pair(ei, e, E, s, d);
    atomicAdd(&g_deg[d], 1);
}

__global__ __launch_bounds__(256)
void scan_bsum_kernel(int n) {
    __shared__ int red[256];
    int i = blockIdx.x * 256 + threadIdx.x;
    red[threadIdx.x] = (i < n) ? g_deg[i] : 0;
    __syncthreads();
    #pragma unroll
    for (int ofs = 128; ofs > 0; ofs >>= 1) {
        if (threadIdx.x < ofs) red[threadIdx.x] += red[threadIdx.x + ofs];
        __syncthreads();
    }
    if (threadIdx.x == 0) g_bsum[blockIdx.x] = red[0];
}

__global__ __launch_bounds__(256)
void scan_boff_kernel(int nb, int n) {
    __shared__ int s[256];
    int t = threadIdx.x;
    int v = (t < nb) ? g_bsum[t] : 0;
    s[t] = v;
    __syncthreads();
    #pragma unroll
    for (int ofs = 1; ofs < 256; ofs <<= 1) {
        int u = (t >= ofs) ? s[t - ofs] : 0;
        __syncthreads();
        s[t] += u;
        __syncthreads();
    }
    g_boff[t] = s[t] - v;                 // exclusive
    if (t == 255) g_off[n] = s[255];      // total edge count
}

__global__ __launch_bounds__(256)
void scan_write_kernel(int n) {
    __shared__ int s[256];
    int t = threadIdx.x;
    int i = blockIdx.x * 256 + t;
    int v = (i < n) ? g_deg[i] : 0;
    s[t] = v;
    __syncthreads();
    #pragma unroll
    for (int ofs = 1; ofs < 256; ofs <<= 1) {
        int u = (t >= ofs) ? s[t - ofs] : 0;
        __syncthreads();
        s[t] += u;
        __syncthreads();
    }
    if (i < n) {
        int off = g_boff[blockIdx.x] + s[t] - v;
        g_off[i] = off;
        g_pos[i] = off;
    }
}

__global__ void fill_kernel(const void* __restrict__ ei, int E) {
    int e = blockIdx.x * blockDim.x + threadIdx.x;
    if (e >= E) return;
    int s, d;
    edge_pair(ei, e, E, s, d);
    int slot = atomicAdd(&g_pos[d], 1);
    g_csr[slot] = s;
}

// ---------------------------------------------------------------------------
// Gather: acc[i] = feat[i] + sum_{j in N(i)} feat[j]  (fp32 accumulate),
// emit fp16. One warp per node, unroll 4 (MLP).
// VEC = float4 chunks per lane (1 -> D=128, 2 -> D=256).
// ---------------------------------------------------------------------------
template<int VEC>
__global__ void gather_half_kernel(const float* __restrict__ feat,
                                   __half* __restrict__ outh, int n) {
    const int D = VEC * 128;
    int w = (blockIdx.x * blockDim.x + threadIdx.x) >> 5;
    const int lane = threadIdx.x & 31;
    if (w >= n) return;

    const int beg = g_off[w];
    const int end = g_off[w + 1];

    float4 acc[VEC];
    #pragma unroll
    for (int v = 0; v < VEC; ++v)
        acc[v] = *reinterpret_cast<const float4*>(feat + (size_t)w * D + v * 128 + lane * 4);

    int i = beg;
    for (; i + 3 < end; i += 4) {
        int s0 = g_csr[i], s1 = g_csr[i + 1], s2 = g_csr[i + 2], s3 = g_csr[i + 3];
        #pragma unroll
        for (int v = 0; v < VEC; ++v) {
            float4 a = *reinterpret_cast<const float4*>(feat + (size_t)s0 * D + v * 128 + lane * 4);
            float4 b = *reinterpret_cast<const float4*>(feat + (size_t)s1 * D + v * 128 + lane * 4);
            float4 c = *reinterpret_cast<const float4*>(feat + (size_t)s2 * D + v * 128 + lane * 4);
            float4 d = *reinterpret_cast<const float4*>(feat + (size_t)s3 * D + v * 128 + lane * 4);
            acc[v].x += (a.x + b.x) + (c.x + d.x);
            acc[v].y += (a.y + b.y) + (c.y + d.y);
            acc[v].z += (a.z + b.z) + (c.z + d.z);
            acc[v].w += (a.w + b.w) + (c.w + d.w);
        }
    }
    for (; i < end; ++i) {
        int s0 = g_csr[i];
        #pragma unroll
        for (int v = 0; v < VEC; ++v) {
            float4 a = *reinterpret_cast<const float4*>(feat + (size_t)s0 * D + v * 128 + lane * 4);
            acc[v].x += a.x;
            acc[v].y += a.y;
            acc[v].z += a.z;
            acc[v].w += a.w;
        }
    }

    #pragma unroll
    for (int v = 0; v < VEC; ++v) {
        __half h[4];
        h[0] = __float2half(acc[v].x);
        h[1] = __float2half(acc[v].y);
        h[2] = __float2half(acc[v].z);
        h[3] = __float2half(acc[v].w);
        *reinterpret_cast<uint2*>(outh + (size_t)w * D + v * 128 + lane * 4) =
            *reinterpret_cast<uint2*>(h);
    }
}

// ---------------------------------------------------------------------------
// mma.sync GEMM: C[M,N] = A[M,K]@B^T (A, B fp16; B transposed [N,K]).
// K, N compile-time; fp32 accumulate, single product.
// CTA tile 128x128, BK=32, 256 threads (8 warps, 2x4), warp tile 64x32.
// cp.async double-buffered smem pipeline. 40KB smem.
// EPI: 0 = fp32 out (no relu), 1 = relu -> fp16, 2 = relu -> fp32.
// ---------------------------------------------------------------------------
template<int EPI, int K, int N>
__global__ __launch_bounds__(256)
void mma_gemm(const __half* __restrict__ A,
              const __half* __restrict__ Bt,
              const float* __restrict__ bias,
              float* __restrict__ outf,
              __half* __restrict__ outh,
              int M) {
    constexpr int BM = 128, BK = 32, LDS = BK + 8;   // pad -> conflict-free ldmatrix
    constexpr int KTILES = K / BK;
    __shared__ __half Ah[2][BM][LDS];
    __shared__ __half Bh[2][BM][LDS];

    const int tid  = threadIdx.x;
    const int wid  = tid >> 5;
    const int lane = tid & 31;
    const int bm = blockIdx.y * 128;
    const int bn = blockIdx.x * 128;

    const int wm = (wid >> 2) * 64;   // warp m offset: 0 or 64
    const int wn = (wid & 3) * 32;    // warp n offset: 0,32,64,96

    const int lane_r = lane & 15;          // ldmatrix row within 16-row group
    const int lane_c = (lane >> 4) * 8;    // k-half

    float acc[4][4][4];
    #pragma unroll
    for (int mf = 0; mf < 4; ++mf)
        #pragma unroll
        for (int nf = 0; nf < 4; ++nf)
            #pragma unroll
            for (int c = 0; c < 4; ++c)
                acc[mf][nf][c] = 0.0f;

    // Global load mapping: row = tid>>2 (0..63) + it*64, col = (tid&3)*8.
    const int g_row0 = tid >> 2;
    const int g_col  = (tid & 3) * 8;

    // Per-thread smem cp.async destinations (byte addresses).
    uint32_t s_ah[2][2], s_bh[2][2];
    #pragma unroll
    for (int b = 0; b < 2; ++b)
        #pragma unroll
        for (int it = 0; it < 2; ++it) {
            const int row = g_row0 + it * 64;
            s_ah[b][it] = smem_u32(&Ah[b][row][g_col]);
            s_bh[b][it] = smem_u32(&Bh[b][row][g_col]);
        }

    // Issue async loads for k-tile kt into buffer b.
    auto load_tile = [&](int kt, int b) {
        const int k0 = kt << 5;
        #pragma unroll
        for (int it = 0; it < 2; ++it) {
            const int row = g_row0 + it * 64;
            const size_t ga = (size_t)(bm + row) * K + k0 + g_col;
            const size_t gb = (size_t)(bn + row) * K + k0 + g_col;
            cp16(s_ah[b][it], A + ga);
            cp16(s_bh[b][it], Bt + gb);
        }
        CP_COMMIT();
    };

    // Prologue: tile 0 in flight.
    load_tile(0, 0);

    #pragma unroll
    for (int kt = 0; kt < KTILES; ++kt) {
        const int buf = kt & 1;

        if (kt + 1 < KTILES) {
            load_tile(kt + 1, buf ^ 1);
            CP_WAIT(1);      // tile kt complete; tile kt+1 may be in flight
        } else {
            CP_WAIT(0);
        }
        __syncthreads();

        const uint32_t ah_base = smem_u32(&Ah[buf][0][0]);
        const uint32_t bh_base = smem_u32(&Bh[buf][0][0]);

        #pragma unroll
        for (int ks = 0; ks < 2; ++ks) {
            const uint32_t a_off = (uint32_t)(ks * 16 + lane_c) * 2;

            uint32_t ah[4][4];
            #pragma unroll
            for (int mf = 0; mf < 4; ++mf) {
                const uint32_t ro = (uint32_t)((wm + mf * 16 + lane_r) * LDS) * 2;
                ldsm_x4(ah[mf], ah_base + ro + a_off);
            }
            uint32_t bh[4][2];
            #pragma unroll
            for (int np = 0; np < 2; ++np) {
                const uint32_t ro = (uint32_t)((wn + np * 16 + lane_r) * LDS) * 2;
                uint32_t r[4];
                ldsm_x4(r, bh_base + ro + a_off);
                bh[np * 2 + 0][0] = r[0]; bh[np * 2 + 0][1] = r[2];
                bh[np * 2 + 1][0] = r[1]; bh[np * 2 + 1][1] = r[3];
            }

            #pragma unroll
            for (int mf = 0; mf < 4; ++mf)
                #pragma unroll
                for (int nf = 0; nf < 4; ++nf)
                    mma16816(acc[mf][nf], ah[mf], bh[nf]);
        }
        __syncthreads();
    }

    // Epilogue. Thread owns rows (gr, gr+8), cols 2*(lane%4)+{0,1} per fragment.
    const int gr = lane >> 2;
    const int gc = (lane & 3) * 2;
    #pragma unroll
    for (int mf = 0; mf < 4; ++mf) {
        const int row0 = bm + wm + mf * 16 + gr;
        const int row1 = row0 + 8;
        #pragma unroll
        for (int nf = 0; nf < 4; ++nf) {
            const int col = bn + wn + nf * 8 + gc;
            const float bz0 = bias[col], bz1 = bias[col + 1];
            float v00 = acc[mf][nf][0] + bz0, v01 = acc[mf][nf][1] + bz1;
            float v10 = acc[mf][nf][2] + bz0, v11 = acc[mf][nf][3] + bz1;
            if (EPI != 0) {
                v00 = fmaxf(v00, 0.f); v01 = fmaxf(v01, 0.f);
                v10 = fmaxf(v10, 0.f); v11 = fmaxf(v11, 0.f);
            }
            if (EPI == 1) {
                if (row0 < M) {
                    __half2 hh; hh.x = __float2half(v00); hh.y = __float2half(v01);
                    *reinterpret_cast<__half2*>(outh + (size_t)row0 * N + col) = hh;
                }
                if (row1 < M) {
                    __half2 hh; hh.x = __float2half(v10); hh.y = __float2half(v11);
                    *reinterpret_cast<__half2*>(outh + (size_t)row1 * N + col) = hh;
                }
            } else {
                if (row0 < M) {
                    float2 v; v.x = v00; v.y = v01;
                    *reinterpret_cast<float2*>(outf + (size_t)row0 * N + col) = v;
                }
                if (row1 < M) {
                    float2 v; v.x = v10; v.y = v11;
                    *reinterpret_cast<float2*>(outf + (size_t)row1 * N + col) = v;
                }
            }
        }
    }
}

// ---------------------------------------------------------------------------
// Launch
// ---------------------------------------------------------------------------
extern "C" void kernel_launch(void* const* d_in, const int* in_sizes, int n_in,
                              void* d_out, int out_size) {
    const float* x    = (const float*)d_in[0];
    const float* W1a  = (const float*)d_in[1];
    const float* b1a  = (const float*)d_in[2];
    const float* W2a  = (const float*)d_in[3];
    const float* b2a  = (const float*)d_in[4];
    const float* W1b  = (const float*)d_in[5];
    const float* b1b  = (const float*)d_in[6];
    const float* W2b  = (const float*)d_in[7];
    const float* b2b  = (const float*)d_in[8];
    const void*  ei   = d_in[9];

    const int M = N_NODES;
    const int E = in_sizes[9] / 2;

    float *F1;
    __half *A, *B, *WT;
    cudaGetSymbolAddress((void**)&F1, g_f1);
    cudaGetSymbolAddress((void**)&A, g_a);
    cudaGetSymbolAddress((void**)&B, g_b);
    cudaGetSymbolAddress((void**)&WT, g_wt);

    float* out = (float*)d_out;
    const int GY = M_PAD / 128;   // 391

    // Index dtype + zero degrees + weight prep + CSR build.
    init_kernel<<<(N_NODES + 255) / 256, 256>>>((const long long*)ei, N_NODES);
    prep_weights_all<<<(196608 + 255) / 256, 256>>>(W1a, W2a, W1b, W2b, WT);
    hist_kernel<<<(E + 255) / 256, 256>>>(ei, E);
    scan_bsum_kernel<<<NB_SCAN, 256>>>(N_NODES);
    scan_boff_kernel<<<1, 256>>>(NB_SCAN, N_NODES);
    scan_write_kernel<<<NB_SCAN, 256>>>(N_NODES);
    fill_kernel<<<(E + 255) / 256, 256>>>(ei, E);

    // ---- Layer 0 ----
    // A = fp16(x + gather(x))
    gather_half_kernel<1><<<(M * 32 + 255) / 256, 256>>>(x, A, M);
    // h1 = relu(A @ W1a + b1a) -> fp16 B      [50000,128]@[128,256]
    mma_gemm<1, 128, 256><<<dim3(2, GY), 256>>>(A, WT + 0 * 65536, b1a, nullptr, B, M);
    // h2 = relu(B @ W2a + b2a) -> fp32 F1     [50000,256]@[256,256]
    mma_gemm<2, 256, 256><<<dim3(2, GY), 256>>>(B, WT + 1 * 65536, b2a, F1, nullptr, M);

    // ---- Layer 1 ----
    // A = fp16(h2 + gather(h2))
    gather_half_kernel<2><<<(M * 32 + 255) / 256, 256>>>(F1, A, M);
    // h3 = relu(A @ W1b + b1b) -> fp16 B      [50000,256]@[256,256]
    mma_gemm<1, 256, 256><<<dim3(2, GY), 256>>>(A, WT + 2 * 65536, b1b, nullptr, B, M);
    // out = B @ W2b + b2b                     [50000,256]@[256,128]
    mma_gemm<0, 256, 128><<<dim3(1, GY), 256>>>(B, WT + 3 * 65536, b2b, out, nullptr, M);
}

// round 14
// speedup vs baseline: 3.3983x; 1.0794x over previous
#include <cuda_runtime.h>
#include <cuda_fp16.h>
#include <cstdint>

// ---------------------------------------------------------------------------
// GIN on GB300 (compute_103-portable):
//   aggregation: CSR build (coalesced 3-phase scan) + warp-per-node gather;
//                layer-1 gather reads/writes fp16 (fp32 accumulate)
//   GEMMs: pure fp16 mma.sync (fp32 accumulate), cp.async double-buffered,
//          K/N compile-time specialized
//   rel_err budget ~4.3e-4 (gate 1e-3)
// ---------------------------------------------------------------------------

#define N_NODES 50000
#define M_PAD   50048      // 128 * 391
#define D_MAX   256
#define E_MAX   (1 << 20)
#define NB_SCAN 196        // ceil(N_NODES / 256)

// Static scratch. Padding rows of g_a/g_b may hold stale data; they only
// influence GEMM output rows >= N_NODES, which are never stored.
__device__ __half g_a[(size_t)M_PAD * D_MAX];          // GEMM A operand
__device__ __half g_b[(size_t)M_PAD * D_MAX];          // GEMM intermediate
__device__ __half g_wt[4][256 * 256];                  // transposed weights [N][K]
__device__ int g_deg[N_NODES];
__device__ int g_off[N_NODES + 1];
__device__ int g_pos[N_NODES];
__device__ int g_csr[E_MAX];
__device__ int g_bsum[256];
__device__ int g_boff[256];
__device__ int g_idx_is64;

// ---------------------------------------------------------------------------
// PTX helpers (portable: ldmatrix + mma.sync + cp.async, sm_80+)
// ---------------------------------------------------------------------------
static __device__ __forceinline__ uint32_t smem_u32(const void* p) {
    uint32_t a;
    asm("{ .reg .u64 t; cvta.to.shared.u64 t, %1; cvt.u32.u64 %0, t; }" : "=r"(a) : "l"(p));
    return a;
}

static __device__ __forceinline__ void ldsm_x4(uint32_t* r, uint32_t addr) {
    asm volatile("ldmatrix.sync.aligned.m8n8.x4.shared.b16 {%0,%1,%2,%3}, [%4];"
                 : "=r"(r[0]), "=r"(r[1]), "=r"(r[2]), "=r"(r[3]) : "r"(addr));
}

static __device__ __forceinline__ void mma16816(float* c, const uint32_t* a, const uint32_t* b) {
    asm volatile("mma.sync.aligned.m16n8k16.row.col.f32.f16.f16.f32 "
                 "{%0,%1,%2,%3}, {%4,%5,%6,%7}, {%8,%9}, {%0,%1,%2,%3};"
                 : "+f"(c[0]), "+f"(c[1]), "+f"(c[2]), "+f"(c[3])
                 : "r"(a[0]), "r"(a[1]), "r"(a[2]), "r"(a[3]), "r"(b[0]), "r"(b[1]));
}

static __device__ __forceinline__ void cp16(uint32_t saddr, const void* gaddr) {
    asm volatile("cp.async.ca.shared.global [%0], [%1], 16;"
                 :: "r"(saddr), "l"(gaddr) : "memory");
}
#define CP_COMMIT()  asm volatile("cp.async.commit_group;" ::: "memory")
#define CP_WAIT(N)   asm volatile("cp.async.wait_group %0;" :: "n"(N) : "memory")

// Fetch edge endpoint pair (src, dst) for edge e, handling int64/int32 data.
static __device__ __forceinline__ void edge_pair(const void* ei, int e, int E, int& s, int& d) {
    if (g_idx_is64) {
        const long long* p = (const long long*)ei;
        s = (int)p[e];
        d = (int)p[e + E];
    } else {
        const int* p = (const int*)ei;
        s = p[e];
        d = p[e + E];
    }
    s = min(max(s, 0), N_NODES - 1);
    d = min(max(d, 0), N_NODES - 1);
}

// ---------------------------------------------------------------------------
// setup: detect index dtype + zero degrees + prep all 4 weights (fused).
// Weight prep: W[K,N] fp32 -> Wt [N,K] fp16 (4 slots of 65536).
// ---------------------------------------------------------------------------
__global__ void setup_kernel(const long long* __restrict__ ei,
                             const float* __restrict__ W1a, const float* __restrict__ W2a,
                             const float* __restrict__ W1b, const float* __restrict__ W2b,
                             __half* __restrict__ wt) {
    int i = blockIdx.x * blockDim.x + threadIdx.x;
    if (i == 0) {
        int is64 = 1;
        #pragma unroll 1
        for (int j = 0; j < 64; ++j) {
            long long v = ei[j];
            if (v < 0 || v >= (long long)N_NODES) { is64 = 0; break; }
        }
        g_idx_is64 = is64;
    }
    if (i < N_NODES) g_deg[i] = 0;

    if (i < 196608) {
        const float* W; int K, N, base, li;
        if (i < 32768)       { W = W1a; K = 128; N = 256; base = 0;         li = i; }
        else if (i < 98304)  { W = W2a; K = 256; N = 256; base = 1 * 65536; li = i - 32768; }
        else if (i < 163840) { W = W1b; K = 256; N = 256; base = 2 * 65536; li = i - 98304; }
        else                 { W = W2b; K = 256; N = 128; base = 3 * 65536; li = i - 163840; }
        int n = li / K, k = li % K;
        wt[base + li] = __float2half(W[(size_t)k * N + n]);
    }
}

// ---------------------------------------------------------------------------
// CSR build: hist -> 3-phase coalesced scan -> fill.
// ---------------------------------------------------------------------------
__global__ void hist_kernel(const void* __restrict__ ei, int E) {
    int e = blockIdx.x * blockDim.x + threadIdx.x;
    if (e >= E) return;
    int s, d;
    edge_pair(ei, e, E, s, d);
    atomicAdd(&g_deg[d], 1);
}

__global__ __launch_bounds__(256)
void scan_bsum_kernel(int n) {
    __shared__ int red[256];
    int i = blockIdx.x * 256 + threadIdx.x;
    red[threadIdx.x] = (i < n) ? g_deg[i] : 0;
    __syncthreads();
    #pragma unroll
    for (int ofs = 128; ofs > 0; ofs >>= 1) {
        if (threadIdx.x < ofs) red[threadIdx.x] += red[threadIdx.x + ofs];
        __syncthreads();
    }
    if (threadIdx.x == 0) g_bsum[blockIdx.x] = red[0];
}

__global__ __launch_bounds__(256)
void scan_boff_kernel(int nb, int n) {
    __shared__ int s[256];
    int t = threadIdx.x;
    int v = (t < nb) ? g_bsum[t] : 0;
    s[t] = v;
    __syncthreads();
    #pragma unroll
    for (int ofs = 1; ofs < 256; ofs <<= 1) {
        int u = (t >= ofs) ? s[t - ofs] : 0;
        __syncthreads();
        s[t] += u;
        __syncthreads();
    }
    g_boff[t] = s[t] - v;                 // exclusive
    if (t == 255) g_off[n] = s[255];      // total edge count
}

__global__ __launch_bounds__(256)
void scan_write_kernel(int n) {
    __shared__ int s[256];
    int t = threadIdx.x;
    int i = blockIdx.x * 256 + t;
    int v = (i < n) ? g_deg[i] : 0;
    s[t] = v;
    __syncthreads();
    #pragma unroll
    for (int ofs = 1; ofs < 256; ofs <<= 1) {
        int u = (t >= ofs) ? s[t - ofs] : 0;
        __syncthreads();
        s[t] += u;
        __syncthreads();
    }
    if (i < n) {
        int off = g_boff[blockIdx.x] + s[t] - v;
        g_off[i] = off;
        g_pos[i] = off;
    }
}

__global__ void fill_kernel(const void* __restrict__ ei, int E) {
    int e = blockIdx.x * blockDim.x + threadIdx.x;
    if (e >= E) return;
    int s, d;
    edge_pair(ei, e, E, s, d);
    int slot = atomicAdd(&g_pos[d], 1);
    g_csr[slot] = s;
}

// ---------------------------------------------------------------------------
// Gather L0: fp32 input (D=128) -> fp16 output. One warp per node, unroll 4.
// ---------------------------------------------------------------------------
__global__ void gather_f2h_128(const float* __restrict__ feat,
                               __half* __restrict__ outh, int n) {
    const int D = 128;
    int w = (blockIdx.x * blockDim.x + threadIdx.x) >> 5;
    const int lane = threadIdx.x & 31;
    if (w >= n) return;

    const int beg = g_off[w];
    const int end = g_off[w + 1];

    float4 acc = *reinterpret_cast<const float4*>(feat + (size_t)w * D + lane * 4);

    int i = beg;
    for (; i + 3 < end; i += 4) {
        int s0 = g_csr[i], s1 = g_csr[i + 1], s2 = g_csr[i + 2], s3 = g_csr[i + 3];
        float4 a = *reinterpret_cast<const float4*>(feat + (size_t)s0 * D + lane * 4);
        float4 b = *reinterpret_cast<const float4*>(feat + (size_t)s1 * D + lane * 4);
        float4 c = *reinterpret_cast<const float4*>(feat + (size_t)s2 * D + lane * 4);
        float4 d = *reinterpret_cast<const float4*>(feat + (size_t)s3 * D + lane * 4);
        acc.x += (a.x + b.x) + (c.x + d.x);
        acc.y += (a.y + b.y) + (c.y + d.y);
        acc.z += (a.z + b.z) + (c.z + d.z);
        acc.w += (a.w + b.w) + (c.w + d.w);
    }
    for (; i < end; ++i) {
        int s0 = g_csr[i];
        float4 a = *reinterpret_cast<const float4*>(feat + (size_t)s0 * D + lane * 4);
        acc.x += a.x; acc.y += a.y; acc.z += a.z; acc.w += a.w;
    }

    __half h[4];
    h[0] = __float2half(acc.x);
    h[1] = __float2half(acc.y);
    h[2] = __float2half(acc.z);
    h[3] = __float2half(acc.w);
    *reinterpret_cast<uint2*>(outh + (size_t)w * D + lane * 4) = *reinterpret_cast<uint2*>(h);
}

// ---------------------------------------------------------------------------
// Gather L1: fp16 input (D=256) -> fp16 output, fp32 accumulate.
// One warp per node; each lane owns 8 halves = one 16B chunk per row.
// ---------------------------------------------------------------------------
__global__ void gather_h2h_256(const __half* __restrict__ feat,
                               __half* __restrict__ outh, int n) {
    const int D = 256;
    int w = (blockIdx.x * blockDim.x + threadIdx.x) >> 5;
    const int lane = threadIdx.x & 31;
    if (w >= n) return;

    const int beg = g_off[w];
    const int end = g_off[w + 1];

    float acc[8];
    {
        uint4 v = *reinterpret_cast<const uint4*>(feat + (size_t)w * D + lane * 8);
        const __half2* p = reinterpret_cast<const __half2*>(&v);
        #pragma unroll
        for (int j = 0; j < 4; ++j) {
            float2 f = __half22float2(p[j]);
            acc[j * 2 + 0] = f.x;
            acc[j * 2 + 1] = f.y;
        }
    }

    int i = beg;
    for (; i + 3 < end; i += 4) {
        int s0 = g_csr[i], s1 = g_csr[i + 1], s2 = g_csr[i + 2], s3 = g_csr[i + 3];
        uint4 va = *reinterpret_cast<const uint4*>(feat + (size_t)s0 * D + lane * 8);
        uint4 vb = *reinterpret_cast<const uint4*>(feat + (size_t)s1 * D + lane * 8);
        uint4 vc = *reinterpret_cast<const uint4*>(feat + (size_t)s2 * D + lane * 8);
        uint4 vd = *reinterpret_cast<const uint4*>(feat + (size_t)s3 * D + lane * 8);
        const __half2* pa = reinterpret_cast<const __half2*>(&va);
        const __half2* pb = reinterpret_cast<const __half2*>(&vb);
        const __half2* pc = reinterpret_cast<const __half2*>(&vc);
        const __half2* pd = reinterpret_cast<const __half2*>(&vd);
        #pragma unroll
        for (int j = 0; j < 4; ++j) {
            float2 fa = __half22float2(pa[j]);
            float2 fb = __half22float2(pb[j]);
            float2 fc = __half22float2(pc[j]);
            float2 fd = __half22float2(pd[j]);
            acc[j * 2 + 0] += (fa.x + fb.x) + (fc.x + fd.x);
            acc[j * 2 + 1] += (fa.y + fb.y) + (fc.y + fd.y);
        }
    }
    for (; i < end; ++i) {
        int s0 = g_csr[i];
        uint4 va = *reinterpret_cast<const uint4*>(feat + (size_t)s0 * D + lane * 8);
        const __half2* pa = reinterpret_cast<const __half2*>(&va);
        #pragma unroll
        for (int j = 0; j < 4; ++j) {
            float2 fa = __half22float2(pa[j]);
            acc[j * 2 + 0] += fa.x;
            acc[j * 2 + 1] += fa.y;
        }
    }

    __half h[8];
    #pragma unroll
    for (int j = 0; j < 8; ++j) h[j] = __float2half(acc[j]);
    *reinterpret_cast<uint4*>(outh + (size_t)w * D + lane * 8) = *reinterpret_cast<uint4*>(h);
}

// ---------------------------------------------------------------------------
// mma.sync GEMM: C[M,N] = A[M,K]@B^T (A, B fp16; B transposed [N,K]).
// K, N compile-time; fp32 accumulate, single product.
// CTA tile 128x128, BK=32, 256 threads (8 warps, 2x4), warp tile 64x32.
// cp.async double-buffered smem pipeline. 40KB smem.
// EPI: 0 = fp32 out (no relu), 1 = relu -> fp16.
// ---------------------------------------------------------------------------
template<int EPI, int K, int N>
__global__ __launch_bounds__(256)
void mma_gemm(const __half* __restrict__ A,
              const __half* __restrict__ Bt,
              const float* __restrict__ bias,
              float* __restrict__ outf,
              __half* __restrict__ outh,
              int M) {
    constexpr int BM = 128, BK = 32, LDS = BK + 8;   // pad -> conflict-free ldmatrix
    constexpr int KTILES = K / BK;
    __shared__ __half Ah[2][BM][LDS];
    __shared__ __half Bh[2][BM][LDS];

    const int tid  = threadIdx.x;
    const int wid  = tid >> 5;
    const int lane = tid & 31;
    const int bm = blockIdx.y * 128;
    const int bn = blockIdx.x * 128;

    const int wm = (wid >> 2) * 64;   // warp m offset: 0 or 64
    const int wn = (wid & 3) * 32;    // warp n offset: 0,32,64,96

    const int lane_r = lane & 15;          // ldmatrix row within 16-row group
    const int lane_c = (lane >> 4) * 8;    // k-half

    float acc[4][4][4];
    #pragma unroll
    for (int mf = 0; mf < 4; ++mf)
        #pragma unroll
        for (int nf = 0; nf < 4; ++nf)
            #pragma unroll
            for (int c = 0; c < 4; ++c)
                acc[mf][nf][c] = 0.0f;

    // Global load mapping: row = tid>>2 (0..63) + it*64, col = (tid&3)*8.
    const int g_row0 = tid >> 2;
    const int g_col  = (tid & 3) * 8;

    // Per-thread smem cp.async destinations (byte addresses).
    uint32_t s_ah[2][2], s_bh[2][2];
    #pragma unroll
    for (int b = 0; b < 2; ++b)
        #pragma unroll
        for (int it = 0; it < 2; ++it) {
            const int row = g_row0 + it * 64;
            s_ah[b][it] = smem_u32(&Ah[b][row][g_col]);
            s_bh[b][it] = smem_u32(&Bh[b][row][g_col]);
        }

    // Issue async loads for k-tile kt into buffer b.
    auto load_tile = [&](int kt, int b) {
        const int k0 = kt << 5;
        #pragma unroll
        for (int it = 0; it < 2; ++it) {
            const int row = g_row0 + it * 64;
            const size_t ga = (size_t)(bm + row) * K + k0 + g_col;
            const size_t gb = (size_t)(bn + row) * K + k0 + g_col;
            cp16(s_ah[b][it], A + ga);
            cp16(s_bh[b][it], Bt + gb);
        }
        CP_COMMIT();
    };

    // Prologue: tile 0 in flight.
    load_tile(0, 0);

    #pragma unroll
    for (int kt = 0; kt < KTILES; ++kt) {
        const int buf = kt & 1;

        if (kt + 1 < KTILES) {
            load_tile(kt + 1, buf ^ 1);
            CP_WAIT(1);      // tile kt complete; tile kt+1 may be in flight
        } else {
            CP_WAIT(0);
        }
        __syncthreads();

        const uint32_t ah_base = smem_u32(&Ah[buf][0][0]);
        const uint32_t bh_base = smem_u32(&Bh[buf][0][0]);

        #pragma unroll
        for (int ks = 0; ks < 2; ++ks) {
            const uint32_t a_off = (uint32_t)(ks * 16 + lane_c) * 2;

            uint32_t ah[4][4];
            #pragma unroll
            for (int mf = 0; mf < 4; ++mf) {
                const uint32_t ro = (uint32_t)((wm + mf * 16 + lane_r) * LDS) * 2;
                ldsm_x4(ah[mf], ah_base + ro + a_off);
            }
            uint32_t bh[4][2];
            #pragma unroll
            for (int np = 0; np < 2; ++np) {
                const uint32_t ro = (uint32_t)((wn + np * 16 + lane_r) * LDS) * 2;
                uint32_t r[4];
                ldsm_x4(r, bh_base + ro + a_off);
                bh[np * 2 + 0][0] = r[0]; bh[np * 2 + 0][1] = r[2];
                bh[np * 2 + 1][0] = r[1]; bh[np * 2 + 1][1] = r[3];
            }

            #pragma unroll
            for (int mf = 0; mf < 4; ++mf)
                #pragma unroll
                for (int nf = 0; nf < 4; ++nf)
                    mma16816(acc[mf][nf], ah[mf], bh[nf]);
        }
        __syncthreads();
    }

    // Epilogue. Thread owns rows (gr, gr+8), cols 2*(lane%4)+{0,1} per fragment.
    const int gr = lane >> 2;
    const int gc = (lane & 3) * 2;
    #pragma unroll
    for (int mf = 0; mf < 4; ++mf) {
        const int row0 = bm + wm + mf * 16 + gr;
        const int row1 = row0 + 8;
        #pragma unroll
        for (int nf = 0; nf < 4; ++nf) {
            const int col = bn + wn + nf * 8 + gc;
            const float bz0 = bias[col], bz1 = bias[col + 1];
            float v00 = acc[mf][nf][0] + bz0, v01 = acc[mf][nf][1] + bz1;
            float v10 = acc[mf][nf][2] + bz0, v11 = acc[mf][nf][3] + bz1;
            if (EPI == 1) {
                v00 = fmaxf(v00, 0.f); v01 = fmaxf(v01, 0.f);
                v10 = fmaxf(v10, 0.f); v11 = fmaxf(v11, 0.f);
                if (row0 < M) {
                    __half2 hh; hh.x = __float2half(v00); hh.y = __float2half(v01);
                    *reinterpret_cast<__half2*>(outh + (size_t)row0 * N + col) = hh;
                }
                if (row1 < M) {
                    __half2 hh; hh.x = __float2half(v10); hh.y = __float2half(v11);
                    *reinterpret_cast<__half2*>(outh + (size_t)row1 * N + col) = hh;
                }
            } else {
                if (row0 < M) {
                    float2 v; v.x = v00; v.y = v01;
                    *reinterpret_cast<float2*>(outf + (size_t)row0 * N + col) = v;
                }
                if (row1 < M) {
                    float2 v; v.x = v10; v.y = v11;
                    *reinterpret_cast<float2*>(outf + (size_t)row1 * N + col) = v;
                }
            }
        }
    }
}

// ---------------------------------------------------------------------------
// Launch
// ---------------------------------------------------------------------------
extern "C" void kernel_launch(void* const* d_in, const int* in_sizes, int n_in,
                              void* d_out, int out_size) {
    const float* x    = (const float*)d_in[0];
    const float* W1a  = (const float*)d_in[1];
    const float* b1a  = (const float*)d_in[2];
    const float* W2a  = (const float*)d_in[3];
    const float* b2a  = (const float*)d_in[4];
    const float* W1b  = (const float*)d_in[5];
    const float* b1b  = (const float*)d_in[6];
    const float* W2b  = (const float*)d_in[7];
    const float* b2b  = (const float*)d_in[8];
    const void*  ei   = d_in[9];

    const int M = N_NODES;
    const int E = in_sizes[9] / 2;

    __half *A, *B, *WT;
    cudaGetSymbolAddress((void**)&A, g_a);
    cudaGetSymbolAddress((void**)&B, g_b);
    cudaGetSymbolAddress((void**)&WT, g_wt);

    float* out = (float*)d_out;
    const int GY = M_PAD / 128;   // 391

    // Setup (idx dtype + zero deg + weight prep) + CSR build.
    setup_kernel<<<768, 256>>>((const long long*)ei, W1a, W2a, W1b, W2b, WT);
    hist_kernel<<<(E + 255) / 256, 256>>>(ei, E);
    scan_bsum_kernel<<<NB_SCAN, 256>>>(N_NODES);
    scan_boff_kernel<<<1, 256>>>(NB_SCAN, N_NODES);
    scan_write_kernel<<<NB_SCAN, 256>>>(N_NODES);
    fill_kernel<<<(E + 255) / 256, 256>>>(ei, E);

    // ---- Layer 0 ----
    // A = fp16(x + gather(x))
    gather_f2h_128<<<(M * 32 + 255) / 256, 256>>>(x, A, M);
    // h1 = relu(A @ W1a + b1a) -> fp16 B      [50000,128]@[128,256]
    mma_gemm<1, 128, 256><<<dim3(2, GY), 256>>>(A, WT + 0 * 65536, b1a, nullptr, B, M);
    // h2 = relu(B @ W2a + b2a) -> fp16 A      [50000,256]@[256,256]
    mma_gemm<1, 256, 256><<<dim3(2, GY), 256>>>(B, WT + 1 * 65536, b2a, nullptr, A, M);

    // ---- Layer 1 ----
    // B = fp16(h2 + gather(h2))   (reads fp16 A, fp32 accumulate)
    gather_h2h_256<<<(M * 32 + 255) / 256, 256>>>(A, B, M);
    // h3 = relu(B @ W1b + b1b) -> fp16 A      [50000,256]@[256,256]
    mma_gemm<1, 256, 256><<<dim3(2, GY), 256>>>(B, WT + 2 * 65536, b1b, nullptr, A, M);
    // out = A @ W2b + b2b                     [50000,256]@[256,128]
    mma_gemm<0, 256, 128><<<dim3(1, GY), 256>>>(A, WT + 3 * 65536, b2b, out, nullptr, M);
}